// round 8
// baseline (speedup 1.0000x reference)
#include <cuda_runtime.h>
#include <cuda_bf16.h>
#include <math.h>
#include <stdint.h>

#define BB 32
#define TT 64
#define FF 128
#define DD 64
#define HH 4
#define KK 32
// (1/sqrt(32)) * log2(e): softmax in log2 domain with ex2
#define QSCALE (0.17677669529663687f * 1.4426950408889634f)

__device__ __forceinline__ float ex2f(float x) {
    float y;
    asm("ex2.approx.ftz.f32 %0, %1;" : "=f"(y) : "f"(x));
    return y;
}

// Split two fp32 into packed bf16 {hi-pair, lo-pair} (v ~= hi + lo, err ~2^-18).
__device__ __forceinline__ uint2 split_u2(float v0, float v1) {
    __nv_bfloat16 h0 = __float2bfloat16(v0);
    __nv_bfloat16 h1 = __float2bfloat16(v1);
    __nv_bfloat16 l0 = __float2bfloat16(v0 - __bfloat162float(h0));
    __nv_bfloat16 l1 = __float2bfloat16(v1 - __bfloat162float(h1));
    __nv_bfloat162 H = __halves2bfloat162(h0, h1);
    __nv_bfloat162 L = __halves2bfloat162(l0, l1);
    uint2 r;
    r.x = *reinterpret_cast<uint32_t*>(&H);
    r.y = *reinterpret_cast<uint32_t*>(&L);
    return r;
}
// Register-side split (for Q, P, O fragments).
__device__ __forceinline__ void split_pk(float v0, float v1, uint32_t& hi, uint32_t& lo) {
    uint2 r = split_u2(v0, v1);
    hi = r.x; lo = r.y;
}

// m16n8k16 bf16 mma, C += A*B (fp32 accum).
__device__ __forceinline__ void mmabf(float* c, const uint32_t* a, const uint32_t* b) {
    asm volatile(
        "mma.sync.aligned.m16n8k16.row.col.f32.bf16.bf16.f32 "
        "{%0,%1,%2,%3}, {%4,%5,%6,%7}, {%8,%9}, {%0,%1,%2,%3};"
        : "+f"(c[0]), "+f"(c[1]), "+f"(c[2]), "+f"(c[3])
        : "r"(a[0]), "r"(a[1]), "r"(a[2]), "r"(a[3]), "r"(b[0]), "r"(b[1]));
}
// 3-term compensated product: C += (Ah+Al)*(Bh+Bl), dropping Al*Bl.
__device__ __forceinline__ void mma3(float* c, const uint32_t* ah, const uint32_t* al,
                                     const uint32_t* bh, const uint32_t* bl) {
    mmabf(c, al, bh);
    mmabf(c, ah, bl);
    mmabf(c, ah, bh);
}

// A fragment from interleaved smem [row][kpair]{hi,lo}: 4x LDS.64.
__device__ __forceinline__ void ldA64(const uint2* p, int W2, int g, int t,
                                      uint32_t* ah, uint32_t* al) {
    uint2 v0 = p[g * W2 + t];
    uint2 v1 = p[(g + 8) * W2 + t];
    uint2 v2 = p[g * W2 + t + 4];
    uint2 v3 = p[(g + 8) * W2 + t + 4];
    ah[0] = v0.x; al[0] = v0.y;
    ah[1] = v1.x; al[1] = v1.y;
    ah[2] = v2.x; al[2] = v2.y;
    ah[3] = v3.x; al[3] = v3.y;
}
// B fragment from interleaved smem [n][kpair]{hi,lo}: 2x LDS.64.
__device__ __forceinline__ void ldB64(const uint2* p, int W2, int g, int t,
                                      uint32_t* bh, uint32_t* bl) {
    uint2 v0 = p[g * W2 + t];
    uint2 v1 = p[g * W2 + t + 4];
    bh[0] = v0.x; bl[0] = v0.y;
    bh[1] = v1.x; bl[1] = v1.y;
}

// ---------------------------------------------------------------------------
// Feature attention: one block per (b, t). 128 rows, 8 warps x 16 rows.
// Q, P, O in registers; X, K, V, weights in interleaved bf16 hi/lo smem.
// ---------------------------------------------------------------------------
__global__ __launch_bounds__(256, 2) void feature_kernel(
    const float* __restrict__ x,
    const float* __restrict__ wq_g, const float* __restrict__ bq_g,
    const float* __restrict__ wk_g, const float* __restrict__ bk_g,
    const float* __restrict__ wv_g, const float* __restrict__ bv_g,
    const float* __restrict__ wo_g, const float* __restrict__ bo_g,
    float* __restrict__ out)
{
    extern __shared__ uint2 smu[];
    uint2* X  = smu;            // 128 x 36   (A-layout [row][dp])
    uint2* WC = smu + 4608;     // 96 x 36    (B-layout [n][dp])
    uint2* WO = smu + 8064;     // 64 x 20    (B-layout [d][vkp])
    uint2* KT = smu + 9344;     // 128 x 20   (B-layout [s][kdp])
    uint2* VT = smu + 11904;    // 32 x 68    (B-layout [vk][sp]); total 14080 u2 = 112640 B

    const int tid  = threadIdx.x;
    const int lane = tid & 31;
    const int w    = tid >> 5;
    const int g    = lane >> 2;
    const int t    = lane & 3;
    const int b    = blockIdx.x >> 6;
    const int tt   = blockIdx.x & 63;
    const int row0 = w * 16;
    const int rrA  = row0 + g, rrB = row0 + g + 8;

    // Stage x slice (contiguous [128][64])
    {
        const float* xp = x + (size_t)(b * TT + tt) * (FF * DD);
        for (int i = tid; i < FF * 32; i += 256) {
            int row = i >> 5, dp = i & 31;
            float2 v = *(const float2*)(xp + row * 64 + 2 * dp);
            X[row * 36 + dp] = split_u2(v.x, v.y);
        }
    }

    float oacc[8][4];
#pragma unroll
    for (int j = 0; j < 8; j++)
#pragma unroll
        for (int i = 0; i < 4; i++) oacc[j][i] = 0.f;

    for (int h = 0; h < HH; h++) {
        __syncthreads();   // guard smem reuse (and x staging on h=0)
        // Stage Wc [n=96][k=64]
        for (int i = tid; i < 96 * 32; i += 256) {
            int n = i % 96, dp = i / 96;
            const float* src = (n < 32) ? wq_g : (n < 64) ? wk_g : wv_g;
            int nn = n & 31;
            float v0 = src[(2 * dp) * 128 + h * 32 + nn];
            float v1 = src[(2 * dp + 1) * 128 + h * 32 + nn];
            WC[n * 36 + dp] = split_u2(v0, v1);
        }
        // Stage Wo [n=d 64][k=vk 32]
        for (int i = tid; i < 64 * 16; i += 256) {
            int d = i & 63, kp = i >> 6;
            float v0 = wo_g[h * 2048 + (2 * kp) * 64 + d];
            float v1 = wo_g[h * 2048 + (2 * kp + 1) * 64 + d];
            WO[d * 20 + kp] = split_u2(v0, v1);
        }
        __syncthreads();

        // --- GEMM1: [16 rows] x [k=64] x [n=96] ---
        float c12[12][4];
#pragma unroll
        for (int j = 0; j < 12; j++)
#pragma unroll
            for (int i = 0; i < 4; i++) c12[j][i] = 0.f;
        for (int kk = 0; kk < 4; kk++) {
            uint32_t ah[4], al[4];
            ldA64(X + row0 * 36 + kk * 8, 36, g, t, ah, al);
#pragma unroll
            for (int j = 0; j < 12; j++) {
                uint32_t bh2[2], bl2[2];
                ldB64(WC + j * 8 * 36 + kk * 8, 36, g, t, bh2, bl2);
                mma3(c12[j], ah, al, bh2, bl2);
            }
        }
        // Epilogue: Q -> registers (A-frag layout), K -> smem, V -> smem transposed
        uint32_t QAh[2][4], QAl[2][4];
#pragma unroll
        for (int j = 0; j < 4; j++) {
            int cc = j * 8 + 2 * t;
            float b0 = bq_g[h * 32 + cc], b1 = bq_g[h * 32 + cc + 1];
            float v0 = (c12[j][0] + b0) * QSCALE, v1 = (c12[j][1] + b1) * QSCALE;
            float v2 = (c12[j][2] + b0) * QSCALE, v3 = (c12[j][3] + b1) * QSCALE;
            int kc = j >> 1, e = j & 1;
            split_pk(v0, v1, QAh[kc][2 * e],     QAl[kc][2 * e]);
            split_pk(v2, v3, QAh[kc][2 * e + 1], QAl[kc][2 * e + 1]);
        }
#pragma unroll
        for (int j = 4; j < 8; j++) {
            int cc = (j - 4) * 8 + 2 * t;
            float b0 = bk_g[h * 32 + cc], b1 = bk_g[h * 32 + cc + 1];
            int kp = cc >> 1;
            KT[rrA * 20 + kp] = split_u2(c12[j][0] + b0, c12[j][1] + b1);
            KT[rrB * 20 + kp] = split_u2(c12[j][2] + b0, c12[j][3] + b1);
        }
        {
            __nv_bfloat16* v16 = reinterpret_cast<__nv_bfloat16*>(VT);
#pragma unroll
            for (int j = 8; j < 12; j++) {
                int vk = (j - 8) * 8 + 2 * t;
                float b0 = bv_g[h * 32 + vk], b1 = bv_g[h * 32 + vk + 1];
                float vv[4] = {c12[j][0] + b0, c12[j][1] + b1, c12[j][2] + b0, c12[j][3] + b1};
                int   cl[4] = {vk, vk + 1, vk, vk + 1};
                int   rw[4] = {rrA, rrA, rrB, rrB};
#pragma unroll
                for (int q2 = 0; q2 < 4; q2++) {
                    __nv_bfloat16 hb = __float2bfloat16(vv[q2]);
                    float lf = vv[q2] - __bfloat162float(hb);
                    int base = (cl[q2] * 68 + (rw[q2] >> 1)) * 4 + (rw[q2] & 1);
                    v16[base]     = hb;
                    v16[base + 2] = __float2bfloat16(lf);
                }
            }
        }
        __syncthreads();   // K, V visible

        // --- S = Q K^T with online softmax, fused PV. 4 chunks of 32 cols ---
        float cP[4][4];
#pragma unroll
        for (int j = 0; j < 4; j++)
#pragma unroll
            for (int i = 0; i < 4; i++) cP[j][i] = 0.f;
        float mrA = -1e30f, mrB = -1e30f, sA = 0.f, sB = 0.f;

        for (int c = 0; c < 4; c++) {
            float cS[4][4];
#pragma unroll
            for (int j = 0; j < 4; j++)
#pragma unroll
                for (int i = 0; i < 4; i++) cS[j][i] = 0.f;
#pragma unroll
            for (int kk = 0; kk < 2; kk++) {
#pragma unroll
                for (int j = 0; j < 4; j++) {
                    uint32_t bh2[2], bl2[2];
                    ldB64(KT + (c * 4 + j) * 8 * 20 + kk * 8, 20, g, t, bh2, bl2);
                    mma3(cS[j], QAh[kk], QAl[kk], bh2, bl2);
                }
            }
            float mA = cS[0][0], mB = cS[0][2];
#pragma unroll
            for (int j = 0; j < 4; j++) {
                mA = fmaxf(mA, fmaxf(cS[j][0], cS[j][1]));
                mB = fmaxf(mB, fmaxf(cS[j][2], cS[j][3]));
            }
            mA = fmaxf(mA, __shfl_xor_sync(0xffffffff, mA, 1));
            mA = fmaxf(mA, __shfl_xor_sync(0xffffffff, mA, 2));
            mB = fmaxf(mB, __shfl_xor_sync(0xffffffff, mB, 1));
            mB = fmaxf(mB, __shfl_xor_sync(0xffffffff, mB, 2));
            float nmA = fmaxf(mrA, mA), nmB = fmaxf(mrB, mB);
            float scA = ex2f(mrA - nmA), scB = ex2f(mrB - nmB);
            float chA = 0.f, chB = 0.f;
#pragma unroll
            for (int j = 0; j < 4; j++) {
                cS[j][0] = ex2f(cS[j][0] - nmA); chA += cS[j][0];
                cS[j][1] = ex2f(cS[j][1] - nmA); chA += cS[j][1];
                cS[j][2] = ex2f(cS[j][2] - nmB); chB += cS[j][2];
                cS[j][3] = ex2f(cS[j][3] - nmB); chB += cS[j][3];
            }
            sA = sA * scA + chA;
            sB = sB * scB + chB;
#pragma unroll
            for (int j = 0; j < 4; j++) {
                cP[j][0] *= scA; cP[j][1] *= scA;
                cP[j][2] *= scB; cP[j][3] *= scB;
            }
            uint32_t ph[2][4], pl[2][4];
#pragma unroll
            for (int k0e = 0; k0e < 2; k0e++) {
                int j0 = 2 * k0e;
                split_pk(cS[j0][0],     cS[j0][1],     ph[k0e][0], pl[k0e][0]);
                split_pk(cS[j0][2],     cS[j0][3],     ph[k0e][1], pl[k0e][1]);
                split_pk(cS[j0 + 1][0], cS[j0 + 1][1], ph[k0e][2], pl[k0e][2]);
                split_pk(cS[j0 + 1][2], cS[j0 + 1][3], ph[k0e][3], pl[k0e][3]);
            }
#pragma unroll
            for (int k0e = 0; k0e < 2; k0e++) {
                int kkv = 2 * c + k0e;
#pragma unroll
                for (int j = 0; j < 4; j++) {
                    uint32_t bh2[2], bl2[2];
                    ldB64(VT + j * 8 * 68 + kkv * 8, 68, g, t, bh2, bl2);
                    mma3(cP[j], ph[k0e], pl[k0e], bh2, bl2);
                }
            }
            mrA = nmA; mrB = nmB;
        }
        sA += __shfl_xor_sync(0xffffffff, sA, 1);
        sA += __shfl_xor_sync(0xffffffff, sA, 2);
        sB += __shfl_xor_sync(0xffffffff, sB, 1);
        sB += __shfl_xor_sync(0xffffffff, sB, 2);
        float invA = __fdividef(1.f, sA), invB = __fdividef(1.f, sB);
#pragma unroll
        for (int j = 0; j < 4; j++) {
            cP[j][0] *= invA; cP[j][1] *= invA;
            cP[j][2] *= invB; cP[j][3] *= invB;
        }

        // O -> registers (A-frag layout), outproj accumulate
        uint32_t OAh[2][4], OAl[2][4];
#pragma unroll
        for (int j = 0; j < 4; j++) {
            int kc = j >> 1, e = j & 1;
            split_pk(cP[j][0], cP[j][1], OAh[kc][2 * e],     OAl[kc][2 * e]);
            split_pk(cP[j][2], cP[j][3], OAh[kc][2 * e + 1], OAl[kc][2 * e + 1]);
        }
#pragma unroll
        for (int kk = 0; kk < 2; kk++) {
#pragma unroll
            for (int j = 0; j < 8; j++) {
                uint32_t bh2[2], bl2[2];
                ldB64(WO + j * 8 * 20 + kk * 8, 20, g, t, bh2, bl2);
                mma3(oacc[j], OAh[kk], OAl[kk], bh2, bl2);
            }
        }
    }

    // Add into out (temporal initialized it). rows = f, cols = d
#pragma unroll
    for (int j = 0; j < 8; j++) {
        int d0 = j * 8 + 2 * t;
        float bo0 = bo_g[d0], bo1 = bo_g[d0 + 1];
        size_t base0 = ((size_t)(b * TT + tt) * FF + rrA) * DD;
        size_t base1 = ((size_t)(b * TT + tt) * FF + rrB) * DD;
        out[base0 + d0]     += oacc[j][0] + bo0;
        out[base0 + d0 + 1] += oacc[j][1] + bo1;
        out[base1 + d0]     += oacc[j][2] + bo0;
        out[base1 + d0 + 1] += oacc[j][3] + bo1;
    }
}

// ---------------------------------------------------------------------------
// Temporal attention: one block per (b, f-pair). 2 sub-blocks x 64 rows (T).
// warps 0-3 -> f0, warps 4-7 -> f0+1. Writes (initializes) out.
// ---------------------------------------------------------------------------
__global__ __launch_bounds__(256, 2) void temporal_kernel(
    const float* __restrict__ x,
    const float* __restrict__ wq_g, const float* __restrict__ bq_g,
    const float* __restrict__ wk_g, const float* __restrict__ bk_g,
    const float* __restrict__ wv_g, const float* __restrict__ bv_g,
    const float* __restrict__ wo_g, const float* __restrict__ bo_g,
    float* __restrict__ out)
{
    extern __shared__ uint2 smu[];
    uint2* X  = smu;            // 2 x (64 x 36)
    uint2* WC = smu + 4608;     // 96 x 36
    uint2* WO = smu + 8064;     // 64 x 20
    uint2* KT = smu + 9344;     // 2 x (64 x 20)
    uint2* VT = smu + 11904;    // 2 x (32 x 36); total 14208 u2 = 113664 B

    const int tid  = threadIdx.x;
    const int lane = tid & 31;
    const int w    = tid >> 5;
    const int g    = lane >> 2;
    const int t    = lane & 3;
    const int b    = blockIdx.x >> 6;
    const int f0   = (blockIdx.x & 63) * 2;
    const int sub  = w >> 2;
    const int row0 = (w & 3) * 16;
    const int rrA  = row0 + g, rrB = row0 + g + 8;
    const int f    = f0 + sub;

    uint2* Xs  = X  + sub * 2304;
    uint2* KTs = KT + sub * 1280;
    uint2* VTs = VT + sub * 1152;

    // Stage x slices for both f's: xs[s][row=t][k=d]
    for (int i = tid; i < 2 * 64 * 32; i += 256) {
        int s = i >> 11, rem = i & 2047, row = rem >> 5, dp = rem & 31;
        const float* xp = x + ((size_t)(b * TT + row) * FF + (f0 + s)) * DD;
        float2 v = *(const float2*)(xp + 2 * dp);
        X[s * 2304 + row * 36 + dp] = split_u2(v.x, v.y);
    }

    float oacc[8][4];
#pragma unroll
    for (int j = 0; j < 8; j++)
#pragma unroll
        for (int i = 0; i < 4; i++) oacc[j][i] = 0.f;

    for (int h = 0; h < HH; h++) {
        __syncthreads();
        for (int i = tid; i < 96 * 32; i += 256) {
            int n = i % 96, dp = i / 96;
            const float* src = (n < 32) ? wq_g : (n < 64) ? wk_g : wv_g;
            int nn = n & 31;
            float v0 = src[(2 * dp) * 128 + h * 32 + nn];
            float v1 = src[(2 * dp + 1) * 128 + h * 32 + nn];
            WC[n * 36 + dp] = split_u2(v0, v1);
        }
        for (int i = tid; i < 64 * 16; i += 256) {
            int d = i & 63, kp = i >> 6;
            float v0 = wo_g[h * 2048 + (2 * kp) * 64 + d];
            float v1 = wo_g[h * 2048 + (2 * kp + 1) * 64 + d];
            WO[d * 20 + kp] = split_u2(v0, v1);
        }
        __syncthreads();

        // --- GEMM1 ---
        float c12[12][4];
#pragma unroll
        for (int j = 0; j < 12; j++)
#pragma unroll
            for (int i = 0; i < 4; i++) c12[j][i] = 0.f;
        for (int kk = 0; kk < 4; kk++) {
            uint32_t ah[4], al[4];
            ldA64(Xs + row0 * 36 + kk * 8, 36, g, t, ah, al);
#pragma unroll
            for (int j = 0; j < 12; j++) {
                uint32_t bh2[2], bl2[2];
                ldB64(WC + j * 8 * 36 + kk * 8, 36, g, t, bh2, bl2);
                mma3(c12[j], ah, al, bh2, bl2);
            }
        }
        uint32_t QAh[2][4], QAl[2][4];
#pragma unroll
        for (int j = 0; j < 4; j++) {
            int cc = j * 8 + 2 * t;
            float b0 = bq_g[h * 32 + cc], b1 = bq_g[h * 32 + cc + 1];
            float v0 = (c12[j][0] + b0) * QSCALE, v1 = (c12[j][1] + b1) * QSCALE;
            float v2 = (c12[j][2] + b0) * QSCALE, v3 = (c12[j][3] + b1) * QSCALE;
            int kc = j >> 1, e = j & 1;
            split_pk(v0, v1, QAh[kc][2 * e],     QAl[kc][2 * e]);
            split_pk(v2, v3, QAh[kc][2 * e + 1], QAl[kc][2 * e + 1]);
        }
#pragma unroll
        for (int j = 4; j < 8; j++) {
            int cc = (j - 4) * 8 + 2 * t;
            float b0 = bk_g[h * 32 + cc], b1 = bk_g[h * 32 + cc + 1];
            int kp = cc >> 1;
            KTs[rrA * 20 + kp] = split_u2(c12[j][0] + b0, c12[j][1] + b1);
            KTs[rrB * 20 + kp] = split_u2(c12[j][2] + b0, c12[j][3] + b1);
        }
        {
            __nv_bfloat16* v16 = reinterpret_cast<__nv_bfloat16*>(VTs);
#pragma unroll
            for (int j = 8; j < 12; j++) {
                int vk = (j - 8) * 8 + 2 * t;
                float b0 = bv_g[h * 32 + vk], b1 = bv_g[h * 32 + vk + 1];
                float vv[4] = {c12[j][0] + b0, c12[j][1] + b1, c12[j][2] + b0, c12[j][3] + b1};
                int   cl[4] = {vk, vk + 1, vk, vk + 1};
                int   rw[4] = {rrA, rrA, rrB, rrB};
#pragma unroll
                for (int q2 = 0; q2 < 4; q2++) {
                    __nv_bfloat16 hb = __float2bfloat16(vv[q2]);
                    float lf = vv[q2] - __bfloat162float(hb);
                    int base = (cl[q2] * 36 + (rw[q2] >> 1)) * 4 + (rw[q2] & 1);
                    v16[base]     = hb;
                    v16[base + 2] = __float2bfloat16(lf);
                }
            }
        }
        __syncthreads();

        // --- S = Q K^T over 64 cols, full-row softmax ---
        float cS[8][4];
#pragma unroll
        for (int j = 0; j < 8; j++)
#pragma unroll
            for (int i = 0; i < 4; i++) cS[j][i] = 0.f;
#pragma unroll
        for (int kk = 0; kk < 2; kk++) {
#pragma unroll
            for (int j = 0; j < 8; j++) {
                uint32_t bh2[2], bl2[2];
                ldB64(KTs + j * 8 * 20 + kk * 8, 20, g, t, bh2, bl2);
                mma3(cS[j], QAh[kk], QAl[kk], bh2, bl2);
            }
        }
        float mA = cS[0][0], mB = cS[0][2];
#pragma unroll
        for (int j = 0; j < 8; j++) {
            mA = fmaxf(mA, fmaxf(cS[j][0], cS[j][1]));
            mB = fmaxf(mB, fmaxf(cS[j][2], cS[j][3]));
        }
        mA = fmaxf(mA, __shfl_xor_sync(0xffffffff, mA, 1));
        mA = fmaxf(mA, __shfl_xor_sync(0xffffffff, mA, 2));
        mB = fmaxf(mB, __shfl_xor_sync(0xffffffff, mB, 1));
        mB = fmaxf(mB, __shfl_xor_sync(0xffffffff, mB, 2));
        float sA = 0.f, sB = 0.f;
#pragma unroll
        for (int j = 0; j < 8; j++) {
            cS[j][0] = ex2f(cS[j][0] - mA); sA += cS[j][0];
            cS[j][1] = ex2f(cS[j][1] - mA); sA += cS[j][1];
            cS[j][2] = ex2f(cS[j][2] - mB); sB += cS[j][2];
            cS[j][3] = ex2f(cS[j][3] - mB); sB += cS[j][3];
        }
        sA += __shfl_xor_sync(0xffffffff, sA, 1);
        sA += __shfl_xor_sync(0xffffffff, sA, 2);
        sB += __shfl_xor_sync(0xffffffff, sB, 1);
        sB += __shfl_xor_sync(0xffffffff, sB, 2);
        float invA = __fdividef(1.f, sA), invB = __fdividef(1.f, sB);

        // P -> registers (A-frags for PV, k = s = 64 -> 4 ksteps)
        uint32_t PAh[4][4], PAl[4][4];
#pragma unroll
        for (int kc = 0; kc < 4; kc++) {
            int j0 = 2 * kc;
            split_pk(cS[j0][0] * invA,     cS[j0][1] * invA,     PAh[kc][0], PAl[kc][0]);
            split_pk(cS[j0][2] * invB,     cS[j0][3] * invB,     PAh[kc][1], PAl[kc][1]);
            split_pk(cS[j0 + 1][0] * invA, cS[j0 + 1][1] * invA, PAh[kc][2], PAl[kc][2]);
            split_pk(cS[j0 + 1][2] * invB, cS[j0 + 1][3] * invB, PAh[kc][3], PAl[kc][3]);
        }

        // --- PV ---
        float cP[4][4];
#pragma unroll
        for (int j = 0; j < 4; j++)
#pragma unroll
            for (int i = 0; i < 4; i++) cP[j][i] = 0.f;
#pragma unroll
        for (int kk = 0; kk < 4; kk++) {
#pragma unroll
            for (int j = 0; j < 4; j++) {
                uint32_t bh2[2], bl2[2];
                ldB64(VTs + j * 8 * 36 + kk * 8, 36, g, t, bh2, bl2);
                mma3(cP[j], PAh[kk], PAl[kk], bh2, bl2);
            }
        }

        // O -> registers, outproj accumulate
        uint32_t OAh[2][4], OAl[2][4];
#pragma unroll
        for (int j = 0; j < 4; j++) {
            int kc = j >> 1, e = j & 1;
            split_pk(cP[j][0], cP[j][1], OAh[kc][2 * e],     OAl[kc][2 * e]);
            split_pk(cP[j][2], cP[j][3], OAh[kc][2 * e + 1], OAl[kc][2 * e + 1]);
        }
#pragma unroll
        for (int kk = 0; kk < 2; kk++) {
#pragma unroll
            for (int j = 0; j < 8; j++) {
                uint32_t bh2[2], bl2[2];
                ldB64(WO + j * 8 * 20 + kk * 8, 20, g, t, bh2, bl2);
                mma3(oacc[j], OAh[kk], OAl[kk], bh2, bl2);
            }
        }
    }

    // Write (initialize) out. rows = t, cols = d
#pragma unroll
    for (int j = 0; j < 8; j++) {
        int d0 = j * 8 + 2 * t;
        float bo0 = bo_g[d0], bo1 = bo_g[d0 + 1];
        size_t base0 = ((size_t)(b * TT + rrA) * FF + f) * DD;
        size_t base1 = ((size_t)(b * TT + rrB) * FF + f) * DD;
        out[base0 + d0]     = oacc[j][0] + bo0;
        out[base0 + d0 + 1] = oacc[j][1] + bo1;
        out[base1 + d0]     = oacc[j][2] + bo0;
        out[base1 + d0 + 1] = oacc[j][3] + bo1;
    }
}

extern "C" void kernel_launch(void* const* d_in, const int* in_sizes, int n_in,
                              void* d_out, int out_size)
{
    const float* x = (const float*)d_in[0];
    const float *tqw, *tqb, *tkw, *tkb, *tvw, *tvb, *tow, *tob;
    const float *fqw, *fqb, *fkw, *fkb, *fvw, *fvb, *fow, *fob;

    if (in_sizes[8] == 64) {  // reference-signature order
        tqw = (const float*)d_in[1];  tqb = (const float*)d_in[2];
        tkw = (const float*)d_in[3];  tkb = (const float*)d_in[4];
        tvw = (const float*)d_in[5];  tvb = (const float*)d_in[6];
        tow = (const float*)d_in[7];  tob = (const float*)d_in[8];
        fqw = (const float*)d_in[9];  fqb = (const float*)d_in[10];
        fkw = (const float*)d_in[11]; fkb = (const float*)d_in[12];
        fvw = (const float*)d_in[13]; fvb = (const float*)d_in[14];
        fow = (const float*)d_in[15]; fob = (const float*)d_in[16];
    } else {                  // setup_inputs dict order
        tqw = (const float*)d_in[1];  tqb = (const float*)d_in[2];
        tkw = (const float*)d_in[3];  tkb = (const float*)d_in[4];
        tvw = (const float*)d_in[5];  tvb = (const float*)d_in[6];
        fqw = (const float*)d_in[7];  fqb = (const float*)d_in[8];
        fkw = (const float*)d_in[9];  fkb = (const float*)d_in[10];
        fvw = (const float*)d_in[11]; fvb = (const float*)d_in[12];
        tow = (const float*)d_in[13]; tob = (const float*)d_in[14];
        fow = (const float*)d_in[15]; fob = (const float*)d_in[16];
    }

    const int SMEM_T = 14208 * 8;   // 113664 B -> 2 CTA/SM
    const int SMEM_F = 14080 * 8;   // 112640 B -> 2 CTA/SM
    cudaFuncSetAttribute(temporal_kernel,
                         cudaFuncAttributeMaxDynamicSharedMemorySize, SMEM_T);
    cudaFuncSetAttribute(feature_kernel,
                         cudaFuncAttributeMaxDynamicSharedMemorySize, SMEM_F);

    temporal_kernel<<<BB * FF / 2, 256, SMEM_T>>>(
        x, tqw, tqb, tkw, tkb, tvw, tvb, tow, tob, (float*)d_out);
    feature_kernel<<<BB * TT, 256, SMEM_F>>>(
        x, fqw, fqb, fkw, fkb, fvw, fvb, fow, fob, (float*)d_out);
}

// round 9
// speedup vs baseline: 1.0642x; 1.0642x over previous
#include <cuda_runtime.h>
#include <cuda_bf16.h>
#include <math.h>
#include <stdint.h>

#define BB 32
#define TT 64
#define FF 128
#define DD 64
#define HH 4
#define KK 32
// (1/sqrt(32)) * log2(e): softmax in log2 domain with ex2
#define QSCALE (0.17677669529663687f * 1.4426950408889634f)

__device__ __forceinline__ float ex2f(float x) {
    float y;
    asm("ex2.approx.ftz.f32 %0, %1;" : "=f"(y) : "f"(x));
    return y;
}

// Permute pair-word index within each 8-word group: word i -> (i&3)*2 + (i>>2).
// After this, a 64-bit load at offset 2t yields (w_t, w_{t+4}) = one mma B-pair.
__device__ __forceinline__ int kperm(int i) {
    return (i & ~7) | ((i & 3) << 1) | ((i >> 2) & 1);
}

// Split two fp32 into packed bf16 hi-pair and lo-pair (v ~= hi + lo, err ~2^-18).
__device__ __forceinline__ void split_pk(float v0, float v1, uint32_t& hi, uint32_t& lo) {
    __nv_bfloat16 h0 = __float2bfloat16(v0);
    __nv_bfloat16 h1 = __float2bfloat16(v1);
    __nv_bfloat16 l0 = __float2bfloat16(v0 - __bfloat162float(h0));
    __nv_bfloat16 l1 = __float2bfloat16(v1 - __bfloat162float(h1));
    __nv_bfloat162 H = __halves2bfloat162(h0, h1);
    __nv_bfloat162 L = __halves2bfloat162(l0, l1);
    hi = *reinterpret_cast<uint32_t*>(&H);
    lo = *reinterpret_cast<uint32_t*>(&L);
}

// m16n8k16 bf16 mma, C += A*B (fp32 accum).
__device__ __forceinline__ void mmabf(float* c, const uint32_t* a, const uint32_t* b) {
    asm volatile(
        "mma.sync.aligned.m16n8k16.row.col.f32.bf16.bf16.f32 "
        "{%0,%1,%2,%3}, {%4,%5,%6,%7}, {%8,%9}, {%0,%1,%2,%3};"
        : "+f"(c[0]), "+f"(c[1]), "+f"(c[2]), "+f"(c[3])
        : "r"(a[0]), "r"(a[1]), "r"(a[2]), "r"(a[3]), "r"(b[0]), "r"(b[1]));
}
// 3-term compensated product: C += (Ah+Al)*(Bh+Bl), dropping Al*Bl.
__device__ __forceinline__ void mma3(float* c, const uint32_t* ah, const uint32_t* al,
                                     const uint32_t* bh, const uint32_t* bl) {
    mmabf(c, al, bh);
    mmabf(c, ah, bl);
    mmabf(c, ah, bh);
}

// A fragment from plain smem [row][kpair], width W (W%32 == 4): 4x LDS.32.
__device__ __forceinline__ void ldAw(const uint32_t* p, int W, int g, int t, uint32_t* a) {
    a[0] = p[g * W + t];
    a[1] = p[(g + 8) * W + t];
    a[2] = p[g * W + t + 4];
    a[3] = p[(g + 8) * W + t + 4];
}
// B fragment from k-permuted smem [n][kpair'], width W (W%32 in {8,24}): 1x LDS.64.
__device__ __forceinline__ void ldB64p(const uint32_t* p, int W, int g, int t, uint32_t* b) {
    uint2 v = *reinterpret_cast<const uint2*>(p + g * W + 2 * t);
    b[0] = v.x;
    b[1] = v.y;
}

// ---------------------------------------------------------------------------
// Feature attention: one block per (b, t). 128 rows, 8 warps x 16 rows.
// Q, P, O in registers; X(A, W=36), WC/WO/KT/VT (B, k-permuted) in smem.
// WC region aliases KT+VT (WC dead after GEMM1).
// ---------------------------------------------------------------------------
__global__ __launch_bounds__(256, 2) void feature_kernel(
    const float* __restrict__ x,
    const float* __restrict__ wq_g, const float* __restrict__ bq_g,
    const float* __restrict__ wk_g, const float* __restrict__ bk_g,
    const float* __restrict__ wv_g, const float* __restrict__ bv_g,
    const float* __restrict__ wo_g, const float* __restrict__ bo_g,
    float* __restrict__ out)
{
    extern __shared__ uint32_t smw[];
    uint32_t* XH  = smw;            // 128 x 36
    uint32_t* XL  = smw + 4608;     // -> 9216
    uint32_t* WOH = smw + 9216;     // 64 x 24 -> 10752
    uint32_t* WOL = smw + 10752;    // -> 12288
    // Region R (12288..23040): WC during GEMM1, then KT+VT
    uint32_t* WCH = smw + 12288;    // 96 x 40 -> 16128
    uint32_t* WCL = smw + 16128;    // -> 19968
    uint32_t* KTH = smw + 12288;    // 128 x 24 -> 15360
    uint32_t* KTL = smw + 15360;    // -> 18432
    uint32_t* VTH = smw + 18432;    // 32 x 72 -> 20736
    uint32_t* VTL = smw + 20736;    // -> 23040 (92160 B)

    const int tid  = threadIdx.x;
    const int lane = tid & 31;
    const int w    = tid >> 5;
    const int g    = lane >> 2;
    const int t    = lane & 3;
    const int b    = blockIdx.x >> 6;
    const int tt   = blockIdx.x & 63;
    const int row0 = w * 16;
    const int rrA  = row0 + g, rrB = row0 + g + 8;

    // Stage x slice (contiguous [128][64])
    {
        const float* xp = x + (size_t)(b * TT + tt) * (FF * DD);
        for (int i = tid; i < FF * 32; i += 256) {
            int row = i >> 5, dp = i & 31;
            float2 v = *(const float2*)(xp + row * 64 + 2 * dp);
            split_pk(v.x, v.y, XH[row * 36 + dp], XL[row * 36 + dp]);
        }
    }

    float oacc[8][4];
#pragma unroll
    for (int j = 0; j < 8; j++)
#pragma unroll
        for (int i = 0; i < 4; i++) oacc[j][i] = 0.f;

    for (int h = 0; h < HH; h++) {
        __syncthreads();   // prior-head KT/VT/WO reads done; x staged (h=0)
        // Stage Wc [n=96][k=64 -> 32 pair-words, permuted]
        for (int i = tid; i < 96 * 32; i += 256) {
            int n = i % 96, dp = i / 96;
            const float* src = (n < 32) ? wq_g : (n < 64) ? wk_g : wv_g;
            int nn = n & 31;
            float v0 = src[(2 * dp) * 128 + h * 32 + nn];
            float v1 = src[(2 * dp + 1) * 128 + h * 32 + nn];
            split_pk(v0, v1, WCH[n * 40 + kperm(dp)], WCL[n * 40 + kperm(dp)]);
        }
        // Stage Wo [n=d 64][k=vk 32 -> 16 pair-words, permuted]
        for (int i = tid; i < 64 * 16; i += 256) {
            int d = i & 63, kp = i >> 6;
            float v0 = wo_g[h * 2048 + (2 * kp) * 64 + d];
            float v1 = wo_g[h * 2048 + (2 * kp + 1) * 64 + d];
            split_pk(v0, v1, WOH[d * 24 + kperm(kp)], WOL[d * 24 + kperm(kp)]);
        }
        __syncthreads();

        // --- GEMM1: [16 rows] x [k=64] x [n=96] ---
        float c12[12][4];
#pragma unroll
        for (int j = 0; j < 12; j++)
#pragma unroll
            for (int i = 0; i < 4; i++) c12[j][i] = 0.f;
        for (int kk = 0; kk < 4; kk++) {
            uint32_t ah[4], al[4];
            ldAw(XH + row0 * 36 + kk * 8, 36, g, t, ah);
            ldAw(XL + row0 * 36 + kk * 8, 36, g, t, al);
#pragma unroll
            for (int j = 0; j < 12; j++) {
                uint32_t bh2[2], bl2[2];
                ldB64p(WCH + j * 8 * 40 + kk * 8, 40, g, t, bh2);
                ldB64p(WCL + j * 8 * 40 + kk * 8, 40, g, t, bl2);
                mma3(c12[j], ah, al, bh2, bl2);
            }
        }
        __syncthreads();   // all WC reads done before KT/VT overwrite region R

        // Epilogue: Q -> registers (A-frag layout), K -> smem, V -> smem transposed
        uint32_t QAh[2][4], QAl[2][4];
#pragma unroll
        for (int j = 0; j < 4; j++) {
            int cc = j * 8 + 2 * t;
            float b0 = bq_g[h * 32 + cc], b1 = bq_g[h * 32 + cc + 1];
            float v0 = (c12[j][0] + b0) * QSCALE, v1 = (c12[j][1] + b1) * QSCALE;
            float v2 = (c12[j][2] + b0) * QSCALE, v3 = (c12[j][3] + b1) * QSCALE;
            int kc = j >> 1, e = j & 1;
            split_pk(v0, v1, QAh[kc][2 * e],     QAl[kc][2 * e]);
            split_pk(v2, v3, QAh[kc][2 * e + 1], QAl[kc][2 * e + 1]);
        }
#pragma unroll
        for (int j = 4; j < 8; j++) {
            int cc = (j - 4) * 8 + 2 * t;
            float b0 = bk_g[h * 32 + cc], b1 = bk_g[h * 32 + cc + 1];
            int kp = kperm(cc >> 1);
            split_pk(c12[j][0] + b0, c12[j][1] + b1, KTH[rrA * 24 + kp], KTL[rrA * 24 + kp]);
            split_pk(c12[j][2] + b0, c12[j][3] + b1, KTH[rrB * 24 + kp], KTL[rrB * 24 + kp]);
        }
        {
            __nv_bfloat16* vh = reinterpret_cast<__nv_bfloat16*>(VTH);
            __nv_bfloat16* vl = reinterpret_cast<__nv_bfloat16*>(VTL);
#pragma unroll
            for (int j = 8; j < 12; j++) {
                int vk = (j - 8) * 8 + 2 * t;
                float b0 = bv_g[h * 32 + vk], b1 = bv_g[h * 32 + vk + 1];
                float vv[4] = {c12[j][0] + b0, c12[j][1] + b1, c12[j][2] + b0, c12[j][3] + b1};
                int   cl[4] = {vk, vk + 1, vk, vk + 1};
                int   rw[4] = {rrA, rrA, rrB, rrB};
#pragma unroll
                for (int q2 = 0; q2 < 4; q2++) {
                    __nv_bfloat16 hb = __float2bfloat16(vv[q2]);
                    float lf = vv[q2] - __bfloat162float(hb);
                    int idx = (cl[q2] * 72 + kperm(rw[q2] >> 1)) * 2 + (rw[q2] & 1);
                    vh[idx] = hb;
                    vl[idx] = __float2bfloat16(lf);
                }
            }
        }
        __syncthreads();   // K, V visible

        // --- S = Q K^T with online softmax, fused PV. 4 chunks of 32 cols ---
        float cP[4][4];
#pragma unroll
        for (int j = 0; j < 4; j++)
#pragma unroll
            for (int i = 0; i < 4; i++) cP[j][i] = 0.f;
        float mrA = -1e30f, mrB = -1e30f, sA = 0.f, sB = 0.f;

        for (int c = 0; c < 4; c++) {
            float cS[4][4];
#pragma unroll
            for (int j = 0; j < 4; j++)
#pragma unroll
                for (int i = 0; i < 4; i++) cS[j][i] = 0.f;
#pragma unroll
            for (int kk = 0; kk < 2; kk++) {
#pragma unroll
                for (int j = 0; j < 4; j++) {
                    uint32_t bh2[2], bl2[2];
                    ldB64p(KTH + (c * 4 + j) * 8 * 24 + kk * 8, 24, g, t, bh2);
                    ldB64p(KTL + (c * 4 + j) * 8 * 24 + kk * 8, 24, g, t, bl2);
                    mma3(cS[j], QAh[kk], QAl[kk], bh2, bl2);
                }
            }
            float mA = cS[0][0], mB = cS[0][2];
#pragma unroll
            for (int j = 0; j < 4; j++) {
                mA = fmaxf(mA, fmaxf(cS[j][0], cS[j][1]));
                mB = fmaxf(mB, fmaxf(cS[j][2], cS[j][3]));
            }
            mA = fmaxf(mA, __shfl_xor_sync(0xffffffff, mA, 1));
            mA = fmaxf(mA, __shfl_xor_sync(0xffffffff, mA, 2));
            mB = fmaxf(mB, __shfl_xor_sync(0xffffffff, mB, 1));
            mB = fmaxf(mB, __shfl_xor_sync(0xffffffff, mB, 2));
            float nmA = fmaxf(mrA, mA), nmB = fmaxf(mrB, mB);
            float scA = ex2f(mrA - nmA), scB = ex2f(mrB - nmB);
            float chA = 0.f, chB = 0.f;
#pragma unroll
            for (int j = 0; j < 4; j++) {
                cS[j][0] = ex2f(cS[j][0] - nmA); chA += cS[j][0];
                cS[j][1] = ex2f(cS[j][1] - nmA); chA += cS[j][1];
                cS[j][2] = ex2f(cS[j][2] - nmB); chB += cS[j][2];
                cS[j][3] = ex2f(cS[j][3] - nmB); chB += cS[j][3];
            }
            sA = sA * scA + chA;
            sB = sB * scB + chB;
#pragma unroll
            for (int j = 0; j < 4; j++) {
                cP[j][0] *= scA; cP[j][1] *= scA;
                cP[j][2] *= scB; cP[j][3] *= scB;
            }
            uint32_t ph[2][4], pl[2][4];
#pragma unroll
            for (int k0e = 0; k0e < 2; k0e++) {
                int j0 = 2 * k0e;
                split_pk(cS[j0][0],     cS[j0][1],     ph[k0e][0], pl[k0e][0]);
                split_pk(cS[j0][2],     cS[j0][3],     ph[k0e][1], pl[k0e][1]);
                split_pk(cS[j0 + 1][0], cS[j0 + 1][1], ph[k0e][2], pl[k0e][2]);
                split_pk(cS[j0 + 1][2], cS[j0 + 1][3], ph[k0e][3], pl[k0e][3]);
            }
#pragma unroll
            for (int k0e = 0; k0e < 2; k0e++) {
                int kkv = 2 * c + k0e;
#pragma unroll
                for (int j = 0; j < 4; j++) {
                    uint32_t bh2[2], bl2[2];
                    ldB64p(VTH + j * 8 * 72 + kkv * 8, 72, g, t, bh2);
                    ldB64p(VTL + j * 8 * 72 + kkv * 8, 72, g, t, bl2);
                    mma3(cP[j], ph[k0e], pl[k0e], bh2, bl2);
                }
            }
            mrA = nmA; mrB = nmB;
        }
        sA += __shfl_xor_sync(0xffffffff, sA, 1);
        sA += __shfl_xor_sync(0xffffffff, sA, 2);
        sB += __shfl_xor_sync(0xffffffff, sB, 1);
        sB += __shfl_xor_sync(0xffffffff, sB, 2);
        float invA = __fdividef(1.f, sA), invB = __fdividef(1.f, sB);
#pragma unroll
        for (int j = 0; j < 4; j++) {
            cP[j][0] *= invA; cP[j][1] *= invA;
            cP[j][2] *= invB; cP[j][3] *= invB;
        }

        // O -> registers (A-frag layout), outproj accumulate
        uint32_t OAh[2][4], OAl[2][4];
#pragma unroll
        for (int j = 0; j < 4; j++) {
            int kc = j >> 1, e = j & 1;
            split_pk(cP[j][0], cP[j][1], OAh[kc][2 * e],     OAl[kc][2 * e]);
            split_pk(cP[j][2], cP[j][3], OAh[kc][2 * e + 1], OAl[kc][2 * e + 1]);
        }
#pragma unroll
        for (int kk = 0; kk < 2; kk++) {
#pragma unroll
            for (int j = 0; j < 8; j++) {
                uint32_t bh2[2], bl2[2];
                ldB64p(WOH + j * 8 * 24 + kk * 8, 24, g, t, bh2);
                ldB64p(WOL + j * 8 * 24 + kk * 8, 24, g, t, bl2);
                mma3(oacc[j], OAh[kk], OAl[kk], bh2, bl2);
            }
        }
    }

    // Add into out (temporal initialized it). rows = f, cols = d
#pragma unroll
    for (int j = 0; j < 8; j++) {
        int d0 = j * 8 + 2 * t;
        float bo0 = bo_g[d0], bo1 = bo_g[d0 + 1];
        size_t base0 = ((size_t)(b * TT + tt) * FF + rrA) * DD;
        size_t base1 = ((size_t)(b * TT + tt) * FF + rrB) * DD;
        out[base0 + d0]     += oacc[j][0] + bo0;
        out[base0 + d0 + 1] += oacc[j][1] + bo1;
        out[base1 + d0]     += oacc[j][2] + bo0;
        out[base1 + d0 + 1] += oacc[j][3] + bo1;
    }
}

// ---------------------------------------------------------------------------
// Temporal attention: one block per (b, f-pair). 2 sub-blocks x 64 rows (T).
// warps 0-3 -> f0, warps 4-7 -> f0+1. Writes (initializes) out.
// ---------------------------------------------------------------------------
__global__ __launch_bounds__(256, 2) void temporal_kernel(
    const float* __restrict__ x,
    const float* __restrict__ wq_g, const float* __restrict__ bq_g,
    const float* __restrict__ wk_g, const float* __restrict__ bk_g,
    const float* __restrict__ wv_g, const float* __restrict__ bv_g,
    const float* __restrict__ wo_g, const float* __restrict__ bo_g,
    float* __restrict__ out)
{
    extern __shared__ uint32_t smw[];
    uint32_t* XH  = smw;            // 2 x (64 x 36)
    uint32_t* XL  = smw + 4608;     // -> 9216
    uint32_t* WOH = smw + 9216;     // 64 x 24 -> 10752
    uint32_t* WOL = smw + 10752;    // -> 12288
    // Region R: WC during GEMM1, then KT+VT
    uint32_t* WCH = smw + 12288;    // 96 x 40 -> 16128
    uint32_t* WCL = smw + 16128;    // -> 19968
    uint32_t* KTH = smw + 12288;    // 2 x (64 x 24) -> 15360
    uint32_t* KTL = smw + 15360;    // -> 18432
    uint32_t* VTH = smw + 18432;    // 2 x (32 x 40) -> 20992
    uint32_t* VTL = smw + 20992;    // -> 23552 (94208 B)

    const int tid  = threadIdx.x;
    const int lane = tid & 31;
    const int w    = tid >> 5;
    const int g    = lane >> 2;
    const int t    = lane & 3;
    const int b    = blockIdx.x >> 6;
    const int f0   = (blockIdx.x & 63) * 2;
    const int sub  = w >> 2;
    const int row0 = (w & 3) * 16;
    const int rrA  = row0 + g, rrB = row0 + g + 8;
    const int f    = f0 + sub;

    uint32_t* XHs  = XH + sub * 2304;
    uint32_t* XLs  = XL + sub * 2304;
    uint32_t* KTHs = KTH + sub * 1536;
    uint32_t* KTLs = KTL + sub * 1536;
    uint32_t* VTHs = VTH + sub * 1280;
    uint32_t* VTLs = VTL + sub * 1280;

    // Stage x slices for both f's: xs[s][row=t][k=d]
    for (int i = tid; i < 2 * 64 * 32; i += 256) {
        int s = i >> 11, rem = i & 2047, row = rem >> 5, dp = rem & 31;
        const float* xp = x + ((size_t)(b * TT + row) * FF + (f0 + s)) * DD;
        float2 v = *(const float2*)(xp + 2 * dp);
        split_pk(v.x, v.y, XH[s * 2304 + row * 36 + dp], XL[s * 2304 + row * 36 + dp]);
    }

    float oacc[8][4];
#pragma unroll
    for (int j = 0; j < 8; j++)
#pragma unroll
        for (int i = 0; i < 4; i++) oacc[j][i] = 0.f;

    for (int h = 0; h < HH; h++) {
        __syncthreads();
        for (int i = tid; i < 96 * 32; i += 256) {
            int n = i % 96, dp = i / 96;
            const float* src = (n < 32) ? wq_g : (n < 64) ? wk_g : wv_g;
            int nn = n & 31;
            float v0 = src[(2 * dp) * 128 + h * 32 + nn];
            float v1 = src[(2 * dp + 1) * 128 + h * 32 + nn];
            split_pk(v0, v1, WCH[n * 40 + kperm(dp)], WCL[n * 40 + kperm(dp)]);
        }
        for (int i = tid; i < 64 * 16; i += 256) {
            int d = i & 63, kp = i >> 6;
            float v0 = wo_g[h * 2048 + (2 * kp) * 64 + d];
            float v1 = wo_g[h * 2048 + (2 * kp + 1) * 64 + d];
            split_pk(v0, v1, WOH[d * 24 + kperm(kp)], WOL[d * 24 + kperm(kp)]);
        }
        __syncthreads();

        // --- GEMM1 ---
        float c12[12][4];
#pragma unroll
        for (int j = 0; j < 12; j++)
#pragma unroll
            for (int i = 0; i < 4; i++) c12[j][i] = 0.f;
        for (int kk = 0; kk < 4; kk++) {
            uint32_t ah[4], al[4];
            ldAw(XHs + row0 * 36 + kk * 8, 36, g, t, ah);
            ldAw(XLs + row0 * 36 + kk * 8, 36, g, t, al);
#pragma unroll
            for (int j = 0; j < 12; j++) {
                uint32_t bh2[2], bl2[2];
                ldB64p(WCH + j * 8 * 40 + kk * 8, 40, g, t, bh2);
                ldB64p(WCL + j * 8 * 40 + kk * 8, 40, g, t, bl2);
                mma3(c12[j], ah, al, bh2, bl2);
            }
        }
        __syncthreads();   // WC reads done before KT/VT overwrite

        uint32_t QAh[2][4], QAl[2][4];
#pragma unroll
        for (int j = 0; j < 4; j++) {
            int cc = j * 8 + 2 * t;
            float b0 = bq_g[h * 32 + cc], b1 = bq_g[h * 32 + cc + 1];
            float v0 = (c12[j][0] + b0) * QSCALE, v1 = (c12[j][1] + b1) * QSCALE;
            float v2 = (c12[j][2] + b0) * QSCALE, v3 = (c12[j][3] + b1) * QSCALE;
            int kc = j >> 1, e = j & 1;
            split_pk(v0, v1, QAh[kc][2 * e],     QAl[kc][2 * e]);
            split_pk(v2, v3, QAh[kc][2 * e + 1], QAl[kc][2 * e + 1]);
        }
#pragma unroll
        for (int j = 4; j < 8; j++) {
            int cc = (j - 4) * 8 + 2 * t;
            float b0 = bk_g[h * 32 + cc], b1 = bk_g[h * 32 + cc + 1];
            int kp = kperm(cc >> 1);
            split_pk(c12[j][0] + b0, c12[j][1] + b1, KTHs[rrA * 24 + kp], KTLs[rrA * 24 + kp]);
            split_pk(c12[j][2] + b0, c12[j][3] + b1, KTHs[rrB * 24 + kp], KTLs[rrB * 24 + kp]);
        }
        {
            __nv_bfloat16* vh = reinterpret_cast<__nv_bfloat16*>(VTHs);
            __nv_bfloat16* vl = reinterpret_cast<__nv_bfloat16*>(VTLs);
#pragma unroll
            for (int j = 8; j < 12; j++) {
                int vk = (j - 8) * 8 + 2 * t;
                float b0 = bv_g[h * 32 + vk], b1 = bv_g[h * 32 + vk + 1];
                float vv[4] = {c12[j][0] + b0, c12[j][1] + b1, c12[j][2] + b0, c12[j][3] + b1};
                int   cl[4] = {vk, vk + 1, vk, vk + 1};
                int   rw[4] = {rrA, rrA, rrB, rrB};
#pragma unroll
                for (int q2 = 0; q2 < 4; q2++) {
                    __nv_bfloat16 hb = __float2bfloat16(vv[q2]);
                    float lf = vv[q2] - __bfloat162float(hb);
                    int idx = (cl[q2] * 40 + kperm(rw[q2] >> 1)) * 2 + (rw[q2] & 1);
                    vh[idx] = hb;
                    vl[idx] = __float2bfloat16(lf);
                }
            }
        }
        __syncthreads();

        // --- S = Q K^T over 64 cols, full-row softmax ---
        float cS[8][4];
#pragma unroll
        for (int j = 0; j < 8; j++)
#pragma unroll
            for (int i = 0; i < 4; i++) cS[j][i] = 0.f;
#pragma unroll
        for (int kk = 0; kk < 2; kk++) {
#pragma unroll
            for (int j = 0; j < 8; j++) {
                uint32_t bh2[2], bl2[2];
                ldB64p(KTHs + j * 8 * 24 + kk * 8, 24, g, t, bh2);
                ldB64p(KTLs + j * 8 * 24 + kk * 8, 24, g, t, bl2);
                mma3(cS[j], QAh[kk], QAl[kk], bh2, bl2);
            }
        }
        float mA = cS[0][0], mB = cS[0][2];
#pragma unroll
        for (int j = 0; j < 8; j++) {
            mA = fmaxf(mA, fmaxf(cS[j][0], cS[j][1]));
            mB = fmaxf(mB, fmaxf(cS[j][2], cS[j][3]));
        }
        mA = fmaxf(mA, __shfl_xor_sync(0xffffffff, mA, 1));
        mA = fmaxf(mA, __shfl_xor_sync(0xffffffff, mA, 2));
        mB = fmaxf(mB, __shfl_xor_sync(0xffffffff, mB, 1));
        mB = fmaxf(mB, __shfl_xor_sync(0xffffffff, mB, 2));
        float sA = 0.f, sB = 0.f;
#pragma unroll
        for (int j = 0; j < 8; j++) {
            cS[j][0] = ex2f(cS[j][0] - mA); sA += cS[j][0];
            cS[j][1] = ex2f(cS[j][1] - mA); sA += cS[j][1];
            cS[j][2] = ex2f(cS[j][2] - mB); sB += cS[j][2];
            cS[j][3] = ex2f(cS[j][3] - mB); sB += cS[j][3];
        }
        sA += __shfl_xor_sync(0xffffffff, sA, 1);
        sA += __shfl_xor_sync(0xffffffff, sA, 2);
        sB += __shfl_xor_sync(0xffffffff, sB, 1);
        sB += __shfl_xor_sync(0xffffffff, sB, 2);
        float invA = __fdividef(1.f, sA), invB = __fdividef(1.f, sB);

        // P -> registers (A-frags for PV, k = s = 64 -> 4 ksteps)
        uint32_t PAh[4][4], PAl[4][4];
#pragma unroll
        for (int kc = 0; kc < 4; kc++) {
            int j0 = 2 * kc;
            split_pk(cS[j0][0] * invA,     cS[j0][1] * invA,     PAh[kc][0], PAl[kc][0]);
            split_pk(cS[j0][2] * invB,     cS[j0][3] * invB,     PAh[kc][1], PAl[kc][1]);
            split_pk(cS[j0 + 1][0] * invA, cS[j0 + 1][1] * invA, PAh[kc][2], PAl[kc][2]);
            split_pk(cS[j0 + 1][2] * invB, cS[j0 + 1][3] * invB, PAh[kc][3], PAl[kc][3]);
        }

        // --- PV ---
        float cP[4][4];
#pragma unroll
        for (int j = 0; j < 4; j++)
#pragma unroll
            for (int i = 0; i < 4; i++) cP[j][i] = 0.f;
#pragma unroll
        for (int kk = 0; kk < 4; kk++) {
#pragma unroll
            for (int j = 0; j < 4; j++) {
                uint32_t bh2[2], bl2[2];
                ldB64p(VTHs + j * 8 * 40 + kk * 8, 40, g, t, bh2);
                ldB64p(VTLs + j * 8 * 40 + kk * 8, 40, g, t, bl2);
                mma3(cP[j], PAh[kk], PAl[kk], bh2, bl2);
            }
        }

        // O -> registers, outproj accumulate
        uint32_t OAh[2][4], OAl[2][4];
#pragma unroll
        for (int j = 0; j < 4; j++) {
            int kc = j >> 1, e = j & 1;
            split_pk(cP[j][0], cP[j][1], OAh[kc][2 * e],     OAl[kc][2 * e]);
            split_pk(cP[j][2], cP[j][3], OAh[kc][2 * e + 1], OAl[kc][2 * e + 1]);
        }
#pragma unroll
        for (int kk = 0; kk < 2; kk++) {
#pragma unroll
            for (int j = 0; j < 8; j++) {
                uint32_t bh2[2], bl2[2];
                ldB64p(WOH + j * 8 * 24 + kk * 8, 24, g, t, bh2);
                ldB64p(WOL + j * 8 * 24 + kk * 8, 24, g, t, bl2);
                mma3(oacc[j], OAh[kk], OAl[kk], bh2, bl2);
            }
        }
    }

    // Write (initialize) out. rows = t, cols = d
#pragma unroll
    for (int j = 0; j < 8; j++) {
        int d0 = j * 8 + 2 * t;
        float bo0 = bo_g[d0], bo1 = bo_g[d0 + 1];
        size_t base0 = ((size_t)(b * TT + rrA) * FF + f) * DD;
        size_t base1 = ((size_t)(b * TT + rrB) * FF + f) * DD;
        out[base0 + d0]     = oacc[j][0] + bo0;
        out[base0 + d0 + 1] = oacc[j][1] + bo1;
        out[base1 + d0]     = oacc[j][2] + bo0;
        out[base1 + d0 + 1] = oacc[j][3] + bo1;
    }
}

extern "C" void kernel_launch(void* const* d_in, const int* in_sizes, int n_in,
                              void* d_out, int out_size)
{
    const float* x = (const float*)d_in[0];
    const float *tqw, *tqb, *tkw, *tkb, *tvw, *tvb, *tow, *tob;
    const float *fqw, *fqb, *fkw, *fkb, *fvw, *fvb, *fow, *fob;

    if (in_sizes[8] == 64) {  // reference-signature order
        tqw = (const float*)d_in[1];  tqb = (const float*)d_in[2];
        tkw = (const float*)d_in[3];  tkb = (const float*)d_in[4];
        tvw = (const float*)d_in[5];  tvb = (const float*)d_in[6];
        tow = (const float*)d_in[7];  tob = (const float*)d_in[8];
        fqw = (const float*)d_in[9];  fqb = (const float*)d_in[10];
        fkw = (const float*)d_in[11]; fkb = (const float*)d_in[12];
        fvw = (const float*)d_in[13]; fvb = (const float*)d_in[14];
        fow = (const float*)d_in[15]; fob = (const float*)d_in[16];
    } else {                  // setup_inputs dict order
        tqw = (const float*)d_in[1];  tqb = (const float*)d_in[2];
        tkw = (const float*)d_in[3];  tkb = (const float*)d_in[4];
        tvw = (const float*)d_in[5];  tvb = (const float*)d_in[6];
        fqw = (const float*)d_in[7];  fqb = (const float*)d_in[8];
        fkw = (const float*)d_in[9];  fkb = (const float*)d_in[10];
        fvw = (const float*)d_in[11]; fvb = (const float*)d_in[12];
        tow = (const float*)d_in[13]; tob = (const float*)d_in[14];
        fow = (const float*)d_in[15]; fob = (const float*)d_in[16];
    }

    const int SMEM_T = 23552 * 4;   // 94208 B -> 2 CTA/SM
    const int SMEM_F = 23040 * 4;   // 92160 B -> 2 CTA/SM
    cudaFuncSetAttribute(temporal_kernel,
                         cudaFuncAttributeMaxDynamicSharedMemorySize, SMEM_T);
    cudaFuncSetAttribute(feature_kernel,
                         cudaFuncAttributeMaxDynamicSharedMemorySize, SMEM_F);

    temporal_kernel<<<BB * FF / 2, 256, SMEM_T>>>(
        x, tqw, tqb, tkw, tkb, tvw, tvb, tow, tob, (float*)d_out);
    feature_kernel<<<BB * TT, 256, SMEM_F>>>(
        x, fqw, fqb, fkw, fkb, fvw, fvb, fow, fob, (float*)d_out);
}

// round 10
// speedup vs baseline: 1.1558x; 1.0861x over previous
#include <cuda_runtime.h>
#include <cuda_bf16.h>
#include <math.h>
#include <stdint.h>

#define BB 32
#define TT 64
#define FF 128
#define DD 64
#define HH 4
#define KK 32
// (1/sqrt(32)) * log2(e): softmax in log2 domain with ex2
#define QSCALE (0.17677669529663687f * 1.4426950408889634f)

__device__ __forceinline__ float ex2f(float x) {
    float y;
    asm("ex2.approx.ftz.f32 %0, %1;" : "=f"(y) : "f"(x));
    return y;
}

// Split two fp32 into packed bf16 hi-pair and lo-pair (v ~= hi + lo, err ~2^-18).
__device__ __forceinline__ void split_pk(float v0, float v1, uint32_t& hi, uint32_t& lo) {
    __nv_bfloat16 h0 = __float2bfloat16(v0);
    __nv_bfloat16 h1 = __float2bfloat16(v1);
    __nv_bfloat16 l0 = __float2bfloat16(v0 - __bfloat162float(h0));
    __nv_bfloat16 l1 = __float2bfloat16(v1 - __bfloat162float(h1));
    __nv_bfloat162 H = __halves2bfloat162(h0, h1);
    __nv_bfloat162 L = __halves2bfloat162(l0, l1);
    hi = *reinterpret_cast<uint32_t*>(&H);
    lo = *reinterpret_cast<uint32_t*>(&L);
}

// m16n8k16 bf16 mma, C += A*B (fp32 accum).
__device__ __forceinline__ void mmabf(float* c, const uint32_t* a, const uint32_t* b) {
    asm volatile(
        "mma.sync.aligned.m16n8k16.row.col.f32.bf16.bf16.f32 "
        "{%0,%1,%2,%3}, {%4,%5,%6,%7}, {%8,%9}, {%0,%1,%2,%3};"
        : "+f"(c[0]), "+f"(c[1]), "+f"(c[2]), "+f"(c[3])
        : "r"(a[0]), "r"(a[1]), "r"(a[2]), "r"(a[3]), "r"(b[0]), "r"(b[1]));
}
// 3-term compensated product: C += (Ah+Al)*(Bh+Bl), dropping Al*Bl.
__device__ __forceinline__ void mma3(float* c, const uint32_t* ah, const uint32_t* al,
                                     const uint32_t* bh, const uint32_t* bl) {
    mmabf(c, al, bh);
    mmabf(c, ah, bl);
    mmabf(c, ah, bh);
}

// A fragment from smem [row][kpair], width W: 4x LDS.32.
__device__ __forceinline__ void ldAw(const uint32_t* p, int W, int g, int t, uint32_t* a) {
    a[0] = p[g * W + t];
    a[1] = p[(g + 8) * W + t];
    a[2] = p[g * W + t + 4];
    a[3] = p[(g + 8) * W + t + 4];
}
// B fragment from smem [n][kpair], width W: 2x LDS.32.
__device__ __forceinline__ void ldBw(const uint32_t* p, int W, int g, int t, uint32_t* b) {
    b[0] = p[g * W + t];
    b[1] = p[g * W + t + 4];
}

// ---------------------------------------------------------------------------
// Feature body: id -> (b, t). 128 rows, 8 warps x 16 rows. atomicAdd into out.
// ---------------------------------------------------------------------------
__device__ __forceinline__ void feature_body(
    uint32_t* smw, int id,
    const float* __restrict__ x,
    const float* __restrict__ wq_g, const float* __restrict__ bq_g,
    const float* __restrict__ wk_g, const float* __restrict__ bk_g,
    const float* __restrict__ wv_g, const float* __restrict__ bv_g,
    const float* __restrict__ wo_g, const float* __restrict__ bo_g,
    float* __restrict__ out)
{
    uint32_t* XH  = smw;            // 128 x 36
    uint32_t* XL  = smw + 4608;
    uint32_t* WCH = smw + 9216;     // 96 x 36
    uint32_t* WCL = smw + 12672;
    uint32_t* WOH = smw + 16128;    // 64 x 20
    uint32_t* WOL = smw + 17408;
    uint32_t* KTH = smw + 18688;    // 128 x 20
    uint32_t* KTL = smw + 21248;
    uint32_t* VTH = smw + 23808;    // 32 x 68
    uint32_t* VTL = smw + 25984;    // -> 28160

    const int tid  = threadIdx.x;
    const int lane = tid & 31;
    const int w    = tid >> 5;
    const int g    = lane >> 2;
    const int t    = lane & 3;
    const int b    = id >> 6;
    const int tt   = id & 63;
    const int row0 = w * 16;
    const int rrA  = row0 + g, rrB = row0 + g + 8;

    // Stage x slice (contiguous [128][64])
    {
        const float* xp = x + (size_t)(b * TT + tt) * (FF * DD);
        for (int i = tid; i < FF * 32; i += 256) {
            int row = i >> 5, dp = i & 31;
            float2 v = *(const float2*)(xp + row * 64 + 2 * dp);
            split_pk(v.x, v.y, XH[row * 36 + dp], XL[row * 36 + dp]);
        }
    }

    float oacc[8][4];
#pragma unroll
    for (int j = 0; j < 8; j++)
#pragma unroll
        for (int i = 0; i < 4; i++) oacc[j][i] = 0.f;

    for (int h = 0; h < HH; h++) {
        __syncthreads();
        for (int i = tid; i < 96 * 32; i += 256) {
            int n = i % 96, dp = i / 96;
            const float* src = (n < 32) ? wq_g : (n < 64) ? wk_g : wv_g;
            int nn = n & 31;
            float v0 = src[(2 * dp) * 128 + h * 32 + nn];
            float v1 = src[(2 * dp + 1) * 128 + h * 32 + nn];
            split_pk(v0, v1, WCH[n * 36 + dp], WCL[n * 36 + dp]);
        }
        for (int i = tid; i < 64 * 16; i += 256) {
            int d = i & 63, kp = i >> 6;
            float v0 = wo_g[h * 2048 + (2 * kp) * 64 + d];
            float v1 = wo_g[h * 2048 + (2 * kp + 1) * 64 + d];
            split_pk(v0, v1, WOH[d * 20 + kp], WOL[d * 20 + kp]);
        }
        __syncthreads();

        // --- GEMM1: [16 rows] x [k=64] x [n=96] ---
        float c12[12][4];
#pragma unroll
        for (int j = 0; j < 12; j++)
#pragma unroll
            for (int i = 0; i < 4; i++) c12[j][i] = 0.f;
        for (int kk = 0; kk < 4; kk++) {
            uint32_t ah[4], al[4];
            ldAw(XH + row0 * 36 + kk * 8, 36, g, t, ah);
            ldAw(XL + row0 * 36 + kk * 8, 36, g, t, al);
#pragma unroll
            for (int j = 0; j < 12; j++) {
                uint32_t bh2[2], bl2[2];
                ldBw(WCH + j * 8 * 36 + kk * 8, 36, g, t, bh2);
                ldBw(WCL + j * 8 * 36 + kk * 8, 36, g, t, bl2);
                mma3(c12[j], ah, al, bh2, bl2);
            }
        }
        // Epilogue: Q -> regs, K -> smem, V -> smem transposed
        uint32_t QAh[2][4], QAl[2][4];
#pragma unroll
        for (int j = 0; j < 4; j++) {
            int cc = j * 8 + 2 * t;
            float b0 = bq_g[h * 32 + cc], b1 = bq_g[h * 32 + cc + 1];
            float v0 = (c12[j][0] + b0) * QSCALE, v1 = (c12[j][1] + b1) * QSCALE;
            float v2 = (c12[j][2] + b0) * QSCALE, v3 = (c12[j][3] + b1) * QSCALE;
            int kc = j >> 1, e = j & 1;
            split_pk(v0, v1, QAh[kc][2 * e],     QAl[kc][2 * e]);
            split_pk(v2, v3, QAh[kc][2 * e + 1], QAl[kc][2 * e + 1]);
        }
#pragma unroll
        for (int j = 4; j < 8; j++) {
            int cc = (j - 4) * 8 + 2 * t;
            float b0 = bk_g[h * 32 + cc], b1 = bk_g[h * 32 + cc + 1];
            int kp = cc >> 1;
            split_pk(c12[j][0] + b0, c12[j][1] + b1, KTH[rrA * 20 + kp], KTL[rrA * 20 + kp]);
            split_pk(c12[j][2] + b0, c12[j][3] + b1, KTH[rrB * 20 + kp], KTL[rrB * 20 + kp]);
        }
        {
            __nv_bfloat16* vh = reinterpret_cast<__nv_bfloat16*>(VTH);
            __nv_bfloat16* vl = reinterpret_cast<__nv_bfloat16*>(VTL);
#pragma unroll
            for (int j = 8; j < 12; j++) {
                int vk = (j - 8) * 8 + 2 * t;
                float b0 = bv_g[h * 32 + vk], b1 = bv_g[h * 32 + vk + 1];
                float vv[4] = {c12[j][0] + b0, c12[j][1] + b1, c12[j][2] + b0, c12[j][3] + b1};
                int   cl[4] = {vk, vk + 1, vk, vk + 1};
                int   rw[4] = {rrA, rrA, rrB, rrB};
#pragma unroll
                for (int q2 = 0; q2 < 4; q2++) {
                    __nv_bfloat16 hb = __float2bfloat16(vv[q2]);
                    float lf = vv[q2] - __bfloat162float(hb);
                    vh[cl[q2] * 136 + rw[q2]] = hb;
                    vl[cl[q2] * 136 + rw[q2]] = __float2bfloat16(lf);
                }
            }
        }
        __syncthreads();

        // --- S = Q K^T with online softmax, fused PV. 4 chunks of 32 cols ---
        float cP[4][4];
#pragma unroll
        for (int j = 0; j < 4; j++)
#pragma unroll
            for (int i = 0; i < 4; i++) cP[j][i] = 0.f;
        float mrA = -1e30f, mrB = -1e30f, sA = 0.f, sB = 0.f;

        for (int c = 0; c < 4; c++) {
            float cS[4][4];
#pragma unroll
            for (int j = 0; j < 4; j++)
#pragma unroll
                for (int i = 0; i < 4; i++) cS[j][i] = 0.f;
#pragma unroll
            for (int kk = 0; kk < 2; kk++) {
#pragma unroll
                for (int j = 0; j < 4; j++) {
                    uint32_t bh2[2], bl2[2];
                    ldBw(KTH + (c * 4 + j) * 8 * 20 + kk * 8, 20, g, t, bh2);
                    ldBw(KTL + (c * 4 + j) * 8 * 20 + kk * 8, 20, g, t, bl2);
                    mma3(cS[j], QAh[kk], QAl[kk], bh2, bl2);
                }
            }
            float mA = cS[0][0], mB = cS[0][2];
#pragma unroll
            for (int j = 0; j < 4; j++) {
                mA = fmaxf(mA, fmaxf(cS[j][0], cS[j][1]));
                mB = fmaxf(mB, fmaxf(cS[j][2], cS[j][3]));
            }
            mA = fmaxf(mA, __shfl_xor_sync(0xffffffff, mA, 1));
            mA = fmaxf(mA, __shfl_xor_sync(0xffffffff, mA, 2));
            mB = fmaxf(mB, __shfl_xor_sync(0xffffffff, mB, 1));
            mB = fmaxf(mB, __shfl_xor_sync(0xffffffff, mB, 2));
            float nmA = fmaxf(mrA, mA), nmB = fmaxf(mrB, mB);
            float scA = ex2f(mrA - nmA), scB = ex2f(mrB - nmB);
            float chA = 0.f, chB = 0.f;
#pragma unroll
            for (int j = 0; j < 4; j++) {
                cS[j][0] = ex2f(cS[j][0] - nmA); chA += cS[j][0];
                cS[j][1] = ex2f(cS[j][1] - nmA); chA += cS[j][1];
                cS[j][2] = ex2f(cS[j][2] - nmB); chB += cS[j][2];
                cS[j][3] = ex2f(cS[j][3] - nmB); chB += cS[j][3];
            }
            sA = sA * scA + chA;
            sB = sB * scB + chB;
#pragma unroll
            for (int j = 0; j < 4; j++) {
                cP[j][0] *= scA; cP[j][1] *= scA;
                cP[j][2] *= scB; cP[j][3] *= scB;
            }
            uint32_t ph[2][4], pl[2][4];
#pragma unroll
            for (int k0e = 0; k0e < 2; k0e++) {
                int j0 = 2 * k0e;
                split_pk(cS[j0][0],     cS[j0][1],     ph[k0e][0], pl[k0e][0]);
                split_pk(cS[j0][2],     cS[j0][3],     ph[k0e][1], pl[k0e][1]);
                split_pk(cS[j0 + 1][0], cS[j0 + 1][1], ph[k0e][2], pl[k0e][2]);
                split_pk(cS[j0 + 1][2], cS[j0 + 1][3], ph[k0e][3], pl[k0e][3]);
            }
#pragma unroll
            for (int k0e = 0; k0e < 2; k0e++) {
                int kkv = 2 * c + k0e;
#pragma unroll
                for (int j = 0; j < 4; j++) {
                    uint32_t bh2[2], bl2[2];
                    ldBw(VTH + j * 8 * 68 + kkv * 8, 68, g, t, bh2);
                    ldBw(VTL + j * 8 * 68 + kkv * 8, 68, g, t, bl2);
                    mma3(cP[j], ph[k0e], pl[k0e], bh2, bl2);
                }
            }
            mrA = nmA; mrB = nmB;
        }
        sA += __shfl_xor_sync(0xffffffff, sA, 1);
        sA += __shfl_xor_sync(0xffffffff, sA, 2);
        sB += __shfl_xor_sync(0xffffffff, sB, 1);
        sB += __shfl_xor_sync(0xffffffff, sB, 2);
        float invA = __fdividef(1.f, sA), invB = __fdividef(1.f, sB);
#pragma unroll
        for (int j = 0; j < 4; j++) {
            cP[j][0] *= invA; cP[j][1] *= invA;
            cP[j][2] *= invB; cP[j][3] *= invB;
        }

        // O -> regs, outproj accumulate
        uint32_t OAh[2][4], OAl[2][4];
#pragma unroll
        for (int j = 0; j < 4; j++) {
            int kc = j >> 1, e = j & 1;
            split_pk(cP[j][0], cP[j][1], OAh[kc][2 * e],     OAl[kc][2 * e]);
            split_pk(cP[j][2], cP[j][3], OAh[kc][2 * e + 1], OAl[kc][2 * e + 1]);
        }
#pragma unroll
        for (int kk = 0; kk < 2; kk++) {
#pragma unroll
            for (int j = 0; j < 8; j++) {
                uint32_t bh2[2], bl2[2];
                ldBw(WOH + j * 8 * 20 + kk * 8, 20, g, t, bh2);
                ldBw(WOL + j * 8 * 20 + kk * 8, 20, g, t, bl2);
                mma3(oacc[j], OAh[kk], OAl[kk], bh2, bl2);
            }
        }
    }

    // Deposit into out (zero-initialized by memset). rows = f, cols = d
#pragma unroll
    for (int j = 0; j < 8; j++) {
        int d0 = j * 8 + 2 * t;
        float bo0 = bo_g[d0], bo1 = bo_g[d0 + 1];
        size_t base0 = ((size_t)(b * TT + tt) * FF + rrA) * DD;
        size_t base1 = ((size_t)(b * TT + tt) * FF + rrB) * DD;
        atomicAdd(out + base0 + d0,     oacc[j][0] + bo0);
        atomicAdd(out + base0 + d0 + 1, oacc[j][1] + bo1);
        atomicAdd(out + base1 + d0,     oacc[j][2] + bo0);
        atomicAdd(out + base1 + d0 + 1, oacc[j][3] + bo1);
    }
}

// ---------------------------------------------------------------------------
// Temporal body: id -> (b, f-pair). 2 sub-blocks x 64 rows (T). atomicAdd out.
// ---------------------------------------------------------------------------
__device__ __forceinline__ void temporal_body(
    uint32_t* smw, int id,
    const float* __restrict__ x,
    const float* __restrict__ wq_g, const float* __restrict__ bq_g,
    const float* __restrict__ wk_g, const float* __restrict__ bk_g,
    const float* __restrict__ wv_g, const float* __restrict__ bv_g,
    const float* __restrict__ wo_g, const float* __restrict__ bo_g,
    float* __restrict__ out)
{
    uint32_t* XH  = smw;            // 2 x (64 x 36)
    uint32_t* XL  = smw + 4608;
    uint32_t* WCH = smw + 9216;     // 96 x 36
    uint32_t* WCL = smw + 12672;
    uint32_t* WOH = smw + 16128;    // 64 x 20
    uint32_t* WOL = smw + 17408;
    uint32_t* KTH = smw + 18688;    // 2 x (64 x 20)
    uint32_t* KTL = smw + 21248;
    uint32_t* VTH = smw + 23808;    // 2 x (32 x 36)
    uint32_t* VTL = smw + 26112;    // -> 28416

    const int tid  = threadIdx.x;
    const int lane = tid & 31;
    const int w    = tid >> 5;
    const int g    = lane >> 2;
    const int t    = lane & 3;
    const int b    = id >> 6;
    const int f0   = (id & 63) * 2;
    const int sub  = w >> 2;
    const int row0 = (w & 3) * 16;
    const int rrA  = row0 + g, rrB = row0 + g + 8;
    const int f    = f0 + sub;

    uint32_t* XHs  = XH + sub * 2304;
    uint32_t* XLs  = XL + sub * 2304;
    uint32_t* KTHs = KTH + sub * 1280;
    uint32_t* KTLs = KTL + sub * 1280;
    uint32_t* VTHs = VTH + sub * 1152;
    uint32_t* VTLs = VTL + sub * 1152;

    // Stage x slices for both f's
    for (int i = tid; i < 2 * 64 * 32; i += 256) {
        int s = i >> 11, rem = i & 2047, row = rem >> 5, dp = rem & 31;
        const float* xp = x + ((size_t)(b * TT + row) * FF + (f0 + s)) * DD;
        float2 v = *(const float2*)(xp + 2 * dp);
        split_pk(v.x, v.y, XH[s * 2304 + row * 36 + dp], XL[s * 2304 + row * 36 + dp]);
    }

    float oacc[8][4];
#pragma unroll
    for (int j = 0; j < 8; j++)
#pragma unroll
        for (int i = 0; i < 4; i++) oacc[j][i] = 0.f;

    for (int h = 0; h < HH; h++) {
        __syncthreads();
        for (int i = tid; i < 96 * 32; i += 256) {
            int n = i % 96, dp = i / 96;
            const float* src = (n < 32) ? wq_g : (n < 64) ? wk_g : wv_g;
            int nn = n & 31;
            float v0 = src[(2 * dp) * 128 + h * 32 + nn];
            float v1 = src[(2 * dp + 1) * 128 + h * 32 + nn];
            split_pk(v0, v1, WCH[n * 36 + dp], WCL[n * 36 + dp]);
        }
        for (int i = tid; i < 64 * 16; i += 256) {
            int d = i & 63, kp = i >> 6;
            float v0 = wo_g[h * 2048 + (2 * kp) * 64 + d];
            float v1 = wo_g[h * 2048 + (2 * kp + 1) * 64 + d];
            split_pk(v0, v1, WOH[d * 20 + kp], WOL[d * 20 + kp]);
        }
        __syncthreads();

        // --- GEMM1 ---
        float c12[12][4];
#pragma unroll
        for (int j = 0; j < 12; j++)
#pragma unroll
            for (int i = 0; i < 4; i++) c12[j][i] = 0.f;
        for (int kk = 0; kk < 4; kk++) {
            uint32_t ah[4], al[4];
            ldAw(XHs + row0 * 36 + kk * 8, 36, g, t, ah);
            ldAw(XLs + row0 * 36 + kk * 8, 36, g, t, al);
#pragma unroll
            for (int j = 0; j < 12; j++) {
                uint32_t bh2[2], bl2[2];
                ldBw(WCH + j * 8 * 36 + kk * 8, 36, g, t, bh2);
                ldBw(WCL + j * 8 * 36 + kk * 8, 36, g, t, bl2);
                mma3(c12[j], ah, al, bh2, bl2);
            }
        }
        uint32_t QAh[2][4], QAl[2][4];
#pragma unroll
        for (int j = 0; j < 4; j++) {
            int cc = j * 8 + 2 * t;
            float b0 = bq_g[h * 32 + cc], b1 = bq_g[h * 32 + cc + 1];
            float v0 = (c12[j][0] + b0) * QSCALE, v1 = (c12[j][1] + b1) * QSCALE;
            float v2 = (c12[j][2] + b0) * QSCALE, v3 = (c12[j][3] + b1) * QSCALE;
            int kc = j >> 1, e = j & 1;
            split_pk(v0, v1, QAh[kc][2 * e],     QAl[kc][2 * e]);
            split_pk(v2, v3, QAh[kc][2 * e + 1], QAl[kc][2 * e + 1]);
        }
#pragma unroll
        for (int j = 4; j < 8; j++) {
            int cc = (j - 4) * 8 + 2 * t;
            float b0 = bk_g[h * 32 + cc], b1 = bk_g[h * 32 + cc + 1];
            int kp = cc >> 1;
            split_pk(c12[j][0] + b0, c12[j][1] + b1, KTHs[rrA * 20 + kp], KTLs[rrA * 20 + kp]);
            split_pk(c12[j][2] + b0, c12[j][3] + b1, KTHs[rrB * 20 + kp], KTLs[rrB * 20 + kp]);
        }
        {
            __nv_bfloat16* vh = reinterpret_cast<__nv_bfloat16*>(VTHs);
            __nv_bfloat16* vl = reinterpret_cast<__nv_bfloat16*>(VTLs);
#pragma unroll
            for (int j = 8; j < 12; j++) {
                int vk = (j - 8) * 8 + 2 * t;
                float b0 = bv_g[h * 32 + vk], b1 = bv_g[h * 32 + vk + 1];
                float vv[4] = {c12[j][0] + b0, c12[j][1] + b1, c12[j][2] + b0, c12[j][3] + b1};
                int   cl[4] = {vk, vk + 1, vk, vk + 1};
                int   rw[4] = {rrA, rrA, rrB, rrB};
#pragma unroll
                for (int q2 = 0; q2 < 4; q2++) {
                    __nv_bfloat16 hb = __float2bfloat16(vv[q2]);
                    float lf = vv[q2] - __bfloat162float(hb);
                    vh[cl[q2] * 72 + rw[q2]] = hb;
                    vl[cl[q2] * 72 + rw[q2]] = __float2bfloat16(lf);
                }
            }
        }
        __syncthreads();

        // --- S = Q K^T over 64 cols, full-row softmax ---
        float cS[8][4];
#pragma unroll
        for (int j = 0; j < 8; j++)
#pragma unroll
            for (int i = 0; i < 4; i++) cS[j][i] = 0.f;
#pragma unroll
        for (int kk = 0; kk < 2; kk++) {
#pragma unroll
            for (int j = 0; j < 8; j++) {
                uint32_t bh2[2], bl2[2];
                ldBw(KTHs + j * 8 * 20 + kk * 8, 20, g, t, bh2);
                ldBw(KTLs + j * 8 * 20 + kk * 8, 20, g, t, bl2);
                mma3(cS[j], QAh[kk], QAl[kk], bh2, bl2);
            }
        }
        float mA = cS[0][0], mB = cS[0][2];
#pragma unroll
        for (int j = 0; j < 8; j++) {
            mA = fmaxf(mA, fmaxf(cS[j][0], cS[j][1]));
            mB = fmaxf(mB, fmaxf(cS[j][2], cS[j][3]));
        }
        mA = fmaxf(mA, __shfl_xor_sync(0xffffffff, mA, 1));
        mA = fmaxf(mA, __shfl_xor_sync(0xffffffff, mA, 2));
        mB = fmaxf(mB, __shfl_xor_sync(0xffffffff, mB, 1));
        mB = fmaxf(mB, __shfl_xor_sync(0xffffffff, mB, 2));
        float sA = 0.f, sB = 0.f;
#pragma unroll
        for (int j = 0; j < 8; j++) {
            cS[j][0] = ex2f(cS[j][0] - mA); sA += cS[j][0];
            cS[j][1] = ex2f(cS[j][1] - mA); sA += cS[j][1];
            cS[j][2] = ex2f(cS[j][2] - mB); sB += cS[j][2];
            cS[j][3] = ex2f(cS[j][3] - mB); sB += cS[j][3];
        }
        sA += __shfl_xor_sync(0xffffffff, sA, 1);
        sA += __shfl_xor_sync(0xffffffff, sA, 2);
        sB += __shfl_xor_sync(0xffffffff, sB, 1);
        sB += __shfl_xor_sync(0xffffffff, sB, 2);
        float invA = __fdividef(1.f, sA), invB = __fdividef(1.f, sB);

        // P -> regs (A-frags for PV)
        uint32_t PAh[4][4], PAl[4][4];
#pragma unroll
        for (int kc = 0; kc < 4; kc++) {
            int j0 = 2 * kc;
            split_pk(cS[j0][0] * invA,     cS[j0][1] * invA,     PAh[kc][0], PAl[kc][0]);
            split_pk(cS[j0][2] * invB,     cS[j0][3] * invB,     PAh[kc][1], PAl[kc][1]);
            split_pk(cS[j0 + 1][0] * invA, cS[j0 + 1][1] * invA, PAh[kc][2], PAl[kc][2]);
            split_pk(cS[j0 + 1][2] * invB, cS[j0 + 1][3] * invB, PAh[kc][3], PAl[kc][3]);
        }

        // --- PV ---
        float cP[4][4];
#pragma unroll
        for (int j = 0; j < 4; j++)
#pragma unroll
            for (int i = 0; i < 4; i++) cP[j][i] = 0.f;
#pragma unroll
        for (int kk = 0; kk < 4; kk++) {
#pragma unroll
            for (int j = 0; j < 4; j++) {
                uint32_t bh2[2], bl2[2];
                ldBw(VTHs + j * 8 * 36 + kk * 8, 36, g, t, bh2);
                ldBw(VTLs + j * 8 * 36 + kk * 8, 36, g, t, bl2);
                mma3(cP[j], PAh[kk], PAl[kk], bh2, bl2);
            }
        }

        // O -> regs, outproj accumulate
        uint32_t OAh[2][4], OAl[2][4];
#pragma unroll
        for (int j = 0; j < 4; j++) {
            int kc = j >> 1, e = j & 1;
            split_pk(cP[j][0], cP[j][1], OAh[kc][2 * e],     OAl[kc][2 * e]);
            split_pk(cP[j][2], cP[j][3], OAh[kc][2 * e + 1], OAl[kc][2 * e + 1]);
        }
#pragma unroll
        for (int kk = 0; kk < 2; kk++) {
#pragma unroll
            for (int j = 0; j < 8; j++) {
                uint32_t bh2[2], bl2[2];
                ldBw(WOH + j * 8 * 20 + kk * 8, 20, g, t, bh2);
                ldBw(WOL + j * 8 * 20 + kk * 8, 20, g, t, bl2);
                mma3(oacc[j], OAh[kk], OAl[kk], bh2, bl2);
            }
        }
    }

    // Deposit into out (zero-initialized by memset). rows = t, cols = d
#pragma unroll
    for (int j = 0; j < 8; j++) {
        int d0 = j * 8 + 2 * t;
        float bo0 = bo_g[d0], bo1 = bo_g[d0 + 1];
        size_t base0 = ((size_t)(b * TT + rrA) * FF + f) * DD;
        size_t base1 = ((size_t)(b * TT + rrB) * FF + f) * DD;
        atomicAdd(out + base0 + d0,     oacc[j][0] + bo0);
        atomicAdd(out + base0 + d0 + 1, oacc[j][1] + bo1);
        atomicAdd(out + base1 + d0,     oacc[j][2] + bo0);
        atomicAdd(out + base1 + d0 + 1, oacc[j][3] + bo1);
    }
}

// ---------------------------------------------------------------------------
// Fused kernel: even blocks -> temporal, odd blocks -> feature (interleaved
// so every wave carries both types; out is accumulated via commutative
// float atomicAdds onto a zeroed buffer -> bit-deterministic).
// ---------------------------------------------------------------------------
__global__ __launch_bounds__(256, 2) void fused_kernel(
    const float* __restrict__ x,
    const float* __restrict__ tqw, const float* __restrict__ tqb,
    const float* __restrict__ tkw, const float* __restrict__ tkb,
    const float* __restrict__ tvw, const float* __restrict__ tvb,
    const float* __restrict__ tow, const float* __restrict__ tob,
    const float* __restrict__ fqw, const float* __restrict__ fqb,
    const float* __restrict__ fkw, const float* __restrict__ fkb,
    const float* __restrict__ fvw, const float* __restrict__ fvb,
    const float* __restrict__ fow, const float* __restrict__ fob,
    float* __restrict__ out)
{
    extern __shared__ uint32_t smw[];
    int id = blockIdx.x >> 1;
    if ((blockIdx.x & 1) == 0) {
        temporal_body(smw, id, x, tqw, tqb, tkw, tkb, tvw, tvb, tow, tob, out);
    } else {
        feature_body(smw, id, x, fqw, fqb, fkw, fkb, fvw, fvb, fow, fob, out);
    }
}

extern "C" void kernel_launch(void* const* d_in, const int* in_sizes, int n_in,
                              void* d_out, int out_size)
{
    const float* x = (const float*)d_in[0];
    const float *tqw, *tqb, *tkw, *tkb, *tvw, *tvb, *tow, *tob;
    const float *fqw, *fqb, *fkw, *fkb, *fvw, *fvb, *fow, *fob;

    if (in_sizes[8] == 64) {  // reference-signature order
        tqw = (const float*)d_in[1];  tqb = (const float*)d_in[2];
        tkw = (const float*)d_in[3];  tkb = (const float*)d_in[4];
        tvw = (const float*)d_in[5];  tvb = (const float*)d_in[6];
        tow = (const float*)d_in[7];  tob = (const float*)d_in[8];
        fqw = (const float*)d_in[9];  fqb = (const float*)d_in[10];
        fkw = (const float*)d_in[11]; fkb = (const float*)d_in[12];
        fvw = (const float*)d_in[13]; fvb = (const float*)d_in[14];
        fow = (const float*)d_in[15]; fob = (const float*)d_in[16];
    } else {                  // setup_inputs dict order
        tqw = (const float*)d_in[1];  tqb = (const float*)d_in[2];
        tkw = (const float*)d_in[3];  tkb = (const float*)d_in[4];
        tvw = (const float*)d_in[5];  tvb = (const float*)d_in[6];
        fqw = (const float*)d_in[7];  fqb = (const float*)d_in[8];
        fkw = (const float*)d_in[9];  fkb = (const float*)d_in[10];
        fvw = (const float*)d_in[11]; fvb = (const float*)d_in[12];
        tow = (const float*)d_in[13]; tob = (const float*)d_in[14];
        fow = (const float*)d_in[15]; fob = (const float*)d_in[16];
    }

    const int SMEM = 28416 * 4;     // 113664 B -> 2 CTA/SM
    cudaFuncSetAttribute(fused_kernel,
                         cudaFuncAttributeMaxDynamicSharedMemorySize, SMEM);

    cudaMemsetAsync(d_out, 0, (size_t)out_size * sizeof(float), 0);
    fused_kernel<<<2 * BB * TT + BB * FF / 2 == 6144 ? 4096 : 4096, 256, SMEM>>>(
        x, tqw, tqb, tkw, tkb, tvw, tvb, tow, tob,
        fqw, fqb, fkw, fkb, fvw, fvb, fow, fob, (float*)d_out);
}

// round 11
// speedup vs baseline: 1.3611x; 1.1777x over previous
#include <cuda_runtime.h>
#include <cuda_bf16.h>
#include <math.h>
#include <stdint.h>

#define BB 32
#define TT 64
#define FF 128
#define DD 64
#define HH 4
#define KK 32
// (1/sqrt(32)) * log2(e): softmax in log2 domain with ex2
#define QSCALE (0.17677669529663687f * 1.4426950408889634f)

// Pre-split weight buffer: [side][head][9472 words as uint4]
// words layout per head: [0,3456) WCH | [3456,6912) WCL | [6912,8192) WOH | [8192,9472) WOL
__device__ uint4 g_w[2][4][2368];

__device__ __forceinline__ float ex2f(float x) {
    float y;
    asm("ex2.approx.ftz.f32 %0, %1;" : "=f"(y) : "f"(x));
    return y;
}

// Split two fp32 into packed bf16 hi-pair and lo-pair (v ~= hi + lo, err ~2^-18).
// Packed cvt + exact hi extraction via bit ops; same RN rounding as scalar path.
__device__ __forceinline__ void split_pk(float v0, float v1, uint32_t& hi, uint32_t& lo) {
    uint32_t h;
    asm("cvt.rn.bf16x2.f32 %0, %1, %2;" : "=r"(h) : "f"(v1), "f"(v0));
    float h0f = __uint_as_float(h << 16);
    float h1f = __uint_as_float(h & 0xffff0000u);
    float l0 = v0 - h0f;
    float l1 = v1 - h1f;
    uint32_t l;
    asm("cvt.rn.bf16x2.f32 %0, %1, %2;" : "=r"(l) : "f"(l1), "f"(l0));
    hi = h;
    lo = l;
}

// m16n8k16 bf16 mma, C += A*B (fp32 accum).
__device__ __forceinline__ void mmabf(float* c, const uint32_t* a, const uint32_t* b) {
    asm volatile(
        "mma.sync.aligned.m16n8k16.row.col.f32.bf16.bf16.f32 "
        "{%0,%1,%2,%3}, {%4,%5,%6,%7}, {%8,%9}, {%0,%1,%2,%3};"
        : "+f"(c[0]), "+f"(c[1]), "+f"(c[2]), "+f"(c[3])
        : "r"(a[0]), "r"(a[1]), "r"(a[2]), "r"(a[3]), "r"(b[0]), "r"(b[1]));
}
// 3-term compensated product: C += (Ah+Al)*(Bh+Bl), dropping Al*Bl.
__device__ __forceinline__ void mma3(float* c, const uint32_t* ah, const uint32_t* al,
                                     const uint32_t* bh, const uint32_t* bl) {
    mmabf(c, al, bh);
    mmabf(c, ah, bl);
    mmabf(c, ah, bh);
}

// A fragment from smem [row][kpair], width W: 4x LDS.32.
__device__ __forceinline__ void ldAw(const uint32_t* p, int W, int g, int t, uint32_t* a) {
    a[0] = p[g * W + t];
    a[1] = p[(g + 8) * W + t];
    a[2] = p[g * W + t + 4];
    a[3] = p[(g + 8) * W + t + 4];
}
// B fragment from smem [n][kpair], width W: 2x LDS.32.
__device__ __forceinline__ void ldBw(const uint32_t* p, int W, int g, int t, uint32_t* b) {
    b[0] = p[g * W + t];
    b[1] = p[g * W + t + 4];
}

// ---------------------------------------------------------------------------
// Prep kernel: split all weights once into g_w (smem-staging layout).
// grid = 8 blocks: block = (side<<2)|head.
// ---------------------------------------------------------------------------
__global__ void prep_kernel(
    const float* __restrict__ tqw, const float* __restrict__ tkw,
    const float* __restrict__ tvw, const float* __restrict__ tow,
    const float* __restrict__ fqw, const float* __restrict__ fkw,
    const float* __restrict__ fvw, const float* __restrict__ fow)
{
    int side = blockIdx.x >> 2, h = blockIdx.x & 3;
    const float* wq = side ? fqw : tqw;
    const float* wk = side ? fkw : tkw;
    const float* wv = side ? fvw : tvw;
    const float* wo = side ? fow : tow;
    uint32_t* dstw = (uint32_t*)&g_w[side][h][0];
    int tid = threadIdx.x;
    for (int i = tid; i < 96 * 32; i += 256) {
        int n = i % 96, dp = i / 96;
        const float* src = (n < 32) ? wq : (n < 64) ? wk : wv;
        int nn = n & 31;
        float v0 = src[(2 * dp) * 128 + h * 32 + nn];
        float v1 = src[(2 * dp + 1) * 128 + h * 32 + nn];
        split_pk(v0, v1, dstw[n * 36 + dp], dstw[3456 + n * 36 + dp]);
    }
    for (int i = tid; i < 64 * 16; i += 256) {
        int d = i & 63, kp = i >> 6;
        float v0 = wo[h * 2048 + (2 * kp) * 64 + d];
        float v1 = wo[h * 2048 + (2 * kp + 1) * 64 + d];
        split_pk(v0, v1, dstw[6912 + d * 20 + kp], dstw[8192 + d * 20 + kp]);
    }
}

// ---------------------------------------------------------------------------
// Feature body: id -> (b, t). 128 rows, 8 warps x 16 rows. atomicAdd into out.
// ---------------------------------------------------------------------------
__device__ __forceinline__ void feature_body(
    uint32_t* smw, int id,
    const float* __restrict__ x,
    const uint4* __restrict__ wsrc,     // &g_w[1][0][0]
    const float* __restrict__ bq_g, const float* __restrict__ bk_g,
    const float* __restrict__ bv_g, const float* __restrict__ bo_g,
    float* __restrict__ out)
{
    uint32_t* XH  = smw;            // 128 x 36
    uint32_t* XL  = smw + 4608;
    uint32_t* WCH = smw + 9216;     // 96 x 36
    uint32_t* WCL = smw + 12672;
    uint32_t* WOH = smw + 16128;    // 64 x 20
    uint32_t* WOL = smw + 17408;
    uint32_t* KTH = smw + 18688;    // 128 x 20
    uint32_t* KTL = smw + 21248;
    uint32_t* VTH = smw + 23808;    // 32 x 68
    uint32_t* VTL = smw + 25984;    // -> 28160

    const int tid  = threadIdx.x;
    const int lane = tid & 31;
    const int w    = tid >> 5;
    const int g    = lane >> 2;
    const int t    = lane & 3;
    const int b    = id >> 6;
    const int tt   = id & 63;
    const int row0 = w * 16;
    const int rrA  = row0 + g, rrB = row0 + g + 8;

    // Stage x slice (contiguous [128][64])
    {
        const float* xp = x + (size_t)(b * TT + tt) * (FF * DD);
        for (int i = tid; i < FF * 32; i += 256) {
            int row = i >> 5, dp = i & 31;
            float2 v = *(const float2*)(xp + row * 64 + 2 * dp);
            split_pk(v.x, v.y, XH[row * 36 + dp], XL[row * 36 + dp]);
        }
    }

    float oacc[8][4];
#pragma unroll
    for (int j = 0; j < 8; j++)
#pragma unroll
        for (int i = 0; i < 4; i++) oacc[j][i] = 0.f;

    for (int h = 0; h < HH; h++) {
        __syncthreads();
        // Stage pre-split weights: straight vector copy into WCH..WOL
        {
            const uint4* srcv = wsrc + (size_t)h * 2368;
            uint4* dstv = (uint4*)(smw + 9216);
            for (int i = tid; i < 2368; i += 256) dstv[i] = srcv[i];
        }
        __syncthreads();

        // --- GEMM1: [16 rows] x [k=64] x [n=96] ---
        float c12[12][4];
#pragma unroll
        for (int j = 0; j < 12; j++)
#pragma unroll
            for (int i = 0; i < 4; i++) c12[j][i] = 0.f;
        for (int kk = 0; kk < 4; kk++) {
            uint32_t ah[4], al[4];
            ldAw(XH + row0 * 36 + kk * 8, 36, g, t, ah);
            ldAw(XL + row0 * 36 + kk * 8, 36, g, t, al);
#pragma unroll
            for (int j = 0; j < 12; j++) {
                uint32_t bh2[2], bl2[2];
                ldBw(WCH + j * 8 * 36 + kk * 8, 36, g, t, bh2);
                ldBw(WCL + j * 8 * 36 + kk * 8, 36, g, t, bl2);
                mma3(c12[j], ah, al, bh2, bl2);
            }
        }
        // Epilogue: Q -> regs, K -> smem, V -> smem transposed
        uint32_t QAh[2][4], QAl[2][4];
#pragma unroll
        for (int j = 0; j < 4; j++) {
            int cc = j * 8 + 2 * t;
            float b0 = bq_g[h * 32 + cc], b1 = bq_g[h * 32 + cc + 1];
            float v0 = (c12[j][0] + b0) * QSCALE, v1 = (c12[j][1] + b1) * QSCALE;
            float v2 = (c12[j][2] + b0) * QSCALE, v3 = (c12[j][3] + b1) * QSCALE;
            int kc = j >> 1, e = j & 1;
            split_pk(v0, v1, QAh[kc][2 * e],     QAl[kc][2 * e]);
            split_pk(v2, v3, QAh[kc][2 * e + 1], QAl[kc][2 * e + 1]);
        }
#pragma unroll
        for (int j = 4; j < 8; j++) {
            int cc = (j - 4) * 8 + 2 * t;
            float b0 = bk_g[h * 32 + cc], b1 = bk_g[h * 32 + cc + 1];
            int kp = cc >> 1;
            split_pk(c12[j][0] + b0, c12[j][1] + b1, KTH[rrA * 20 + kp], KTL[rrA * 20 + kp]);
            split_pk(c12[j][2] + b0, c12[j][3] + b1, KTH[rrB * 20 + kp], KTL[rrB * 20 + kp]);
        }
        {
            __nv_bfloat16* vh = reinterpret_cast<__nv_bfloat16*>(VTH);
            __nv_bfloat16* vl = reinterpret_cast<__nv_bfloat16*>(VTL);
#pragma unroll
            for (int j = 8; j < 12; j++) {
                int vk = (j - 8) * 8 + 2 * t;
                float b0 = bv_g[h * 32 + vk], b1 = bv_g[h * 32 + vk + 1];
                float vv[4] = {c12[j][0] + b0, c12[j][1] + b1, c12[j][2] + b0, c12[j][3] + b1};
                int   cl[4] = {vk, vk + 1, vk, vk + 1};
                int   rw[4] = {rrA, rrA, rrB, rrB};
#pragma unroll
                for (int q2 = 0; q2 < 4; q2++) {
                    __nv_bfloat16 hb = __float2bfloat16(vv[q2]);
                    float lf = vv[q2] - __bfloat162float(hb);
                    vh[cl[q2] * 136 + rw[q2]] = hb;
                    vl[cl[q2] * 136 + rw[q2]] = __float2bfloat16(lf);
                }
            }
        }
        __syncthreads();

        // --- S = Q K^T with online softmax, fused PV. 4 chunks of 32 cols ---
        float cP[4][4];
#pragma unroll
        for (int j = 0; j < 4; j++)
#pragma unroll
            for (int i = 0; i < 4; i++) cP[j][i] = 0.f;
        float mrA = -1e30f, mrB = -1e30f, sA = 0.f, sB = 0.f;

        for (int c = 0; c < 4; c++) {
            float cS[4][4];
#pragma unroll
            for (int j = 0; j < 4; j++)
#pragma unroll
                for (int i = 0; i < 4; i++) cS[j][i] = 0.f;
#pragma unroll
            for (int kk = 0; kk < 2; kk++) {
#pragma unroll
                for (int j = 0; j < 4; j++) {
                    uint32_t bh2[2], bl2[2];
                    ldBw(KTH + (c * 4 + j) * 8 * 20 + kk * 8, 20, g, t, bh2);
                    ldBw(KTL + (c * 4 + j) * 8 * 20 + kk * 8, 20, g, t, bl2);
                    mma3(cS[j], QAh[kk], QAl[kk], bh2, bl2);
                }
            }
            float mA = cS[0][0], mB = cS[0][2];
#pragma unroll
            for (int j = 0; j < 4; j++) {
                mA = fmaxf(mA, fmaxf(cS[j][0], cS[j][1]));
                mB = fmaxf(mB, fmaxf(cS[j][2], cS[j][3]));
            }
            mA = fmaxf(mA, __shfl_xor_sync(0xffffffff, mA, 1));
            mA = fmaxf(mA, __shfl_xor_sync(0xffffffff, mA, 2));
            mB = fmaxf(mB, __shfl_xor_sync(0xffffffff, mB, 1));
            mB = fmaxf(mB, __shfl_xor_sync(0xffffffff, mB, 2));
            float nmA = fmaxf(mrA, mA), nmB = fmaxf(mrB, mB);
            float scA = ex2f(mrA - nmA), scB = ex2f(mrB - nmB);
            float chA = 0.f, chB = 0.f;
#pragma unroll
            for (int j = 0; j < 4; j++) {
                cS[j][0] = ex2f(cS[j][0] - nmA); chA += cS[j][0];
                cS[j][1] = ex2f(cS[j][1] - nmA); chA += cS[j][1];
                cS[j][2] = ex2f(cS[j][2] - nmB); chB += cS[j][2];
                cS[j][3] = ex2f(cS[j][3] - nmB); chB += cS[j][3];
            }
            sA = sA * scA + chA;
            sB = sB * scB + chB;
#pragma unroll
            for (int j = 0; j < 4; j++) {
                cP[j][0] *= scA; cP[j][1] *= scA;
                cP[j][2] *= scB; cP[j][3] *= scB;
            }
            uint32_t ph[2][4], pl[2][4];
#pragma unroll
            for (int k0e = 0; k0e < 2; k0e++) {
                int j0 = 2 * k0e;
                split_pk(cS[j0][0],     cS[j0][1],     ph[k0e][0], pl[k0e][0]);
                split_pk(cS[j0][2],     cS[j0][3],     ph[k0e][1], pl[k0e][1]);
                split_pk(cS[j0 + 1][0], cS[j0 + 1][1], ph[k0e][2], pl[k0e][2]);
                split_pk(cS[j0 + 1][2], cS[j0 + 1][3], ph[k0e][3], pl[k0e][3]);
            }
#pragma unroll
            for (int k0e = 0; k0e < 2; k0e++) {
                int kkv = 2 * c + k0e;
#pragma unroll
                for (int j = 0; j < 4; j++) {
                    uint32_t bh2[2], bl2[2];
                    ldBw(VTH + j * 8 * 68 + kkv * 8, 68, g, t, bh2);
                    ldBw(VTL + j * 8 * 68 + kkv * 8, 68, g, t, bl2);
                    mma3(cP[j], ph[k0e], pl[k0e], bh2, bl2);
                }
            }
            mrA = nmA; mrB = nmB;
        }
        sA += __shfl_xor_sync(0xffffffff, sA, 1);
        sA += __shfl_xor_sync(0xffffffff, sA, 2);
        sB += __shfl_xor_sync(0xffffffff, sB, 1);
        sB += __shfl_xor_sync(0xffffffff, sB, 2);
        float invA = __fdividef(1.f, sA), invB = __fdividef(1.f, sB);
#pragma unroll
        for (int j = 0; j < 4; j++) {
            cP[j][0] *= invA; cP[j][1] *= invA;
            cP[j][2] *= invB; cP[j][3] *= invB;
        }

        // O -> regs, outproj accumulate
        uint32_t OAh[2][4], OAl[2][4];
#pragma unroll
        for (int j = 0; j < 4; j++) {
            int kc = j >> 1, e = j & 1;
            split_pk(cP[j][0], cP[j][1], OAh[kc][2 * e],     OAl[kc][2 * e]);
            split_pk(cP[j][2], cP[j][3], OAh[kc][2 * e + 1], OAl[kc][2 * e + 1]);
        }
#pragma unroll
        for (int kk = 0; kk < 2; kk++) {
#pragma unroll
            for (int j = 0; j < 8; j++) {
                uint32_t bh2[2], bl2[2];
                ldBw(WOH + j * 8 * 20 + kk * 8, 20, g, t, bh2);
                ldBw(WOL + j * 8 * 20 + kk * 8, 20, g, t, bl2);
                mma3(oacc[j], OAh[kk], OAl[kk], bh2, bl2);
            }
        }
    }

    // Deposit into out (zero-initialized by memset). rows = f, cols = d
#pragma unroll
    for (int j = 0; j < 8; j++) {
        int d0 = j * 8 + 2 * t;
        float bo0 = bo_g[d0], bo1 = bo_g[d0 + 1];
        size_t base0 = ((size_t)(b * TT + tt) * FF + rrA) * DD;
        size_t base1 = ((size_t)(b * TT + tt) * FF + rrB) * DD;
        atomicAdd(out + base0 + d0,     oacc[j][0] + bo0);
        atomicAdd(out + base0 + d0 + 1, oacc[j][1] + bo1);
        atomicAdd(out + base1 + d0,     oacc[j][2] + bo0);
        atomicAdd(out + base1 + d0 + 1, oacc[j][3] + bo1);
    }
}

// ---------------------------------------------------------------------------
// Temporal body: id -> (b, f-pair). 2 sub-blocks x 64 rows (T). atomicAdd out.
// ---------------------------------------------------------------------------
__device__ __forceinline__ void temporal_body(
    uint32_t* smw, int id,
    const float* __restrict__ x,
    const uint4* __restrict__ wsrc,     // &g_w[0][0][0]
    const float* __restrict__ bq_g, const float* __restrict__ bk_g,
    const float* __restrict__ bv_g, const float* __restrict__ bo_g,
    float* __restrict__ out)
{
    uint32_t* XH  = smw;            // 2 x (64 x 36)
    uint32_t* XL  = smw + 4608;
    uint32_t* WCH = smw + 9216;     // 96 x 36
    uint32_t* WCL = smw + 12672;
    uint32_t* WOH = smw + 16128;    // 64 x 20
    uint32_t* WOL = smw + 17408;
    uint32_t* KTH = smw + 18688;    // 2 x (64 x 20)
    uint32_t* KTL = smw + 21248;
    uint32_t* VTH = smw + 23808;    // 2 x (32 x 36)
    uint32_t* VTL = smw + 26112;    // -> 28416

    const int tid  = threadIdx.x;
    const int lane = tid & 31;
    const int w    = tid >> 5;
    const int g    = lane >> 2;
    const int t    = lane & 3;
    const int b    = id >> 6;
    const int f0   = (id & 63) * 2;
    const int sub  = w >> 2;
    const int row0 = (w & 3) * 16;
    const int rrA  = row0 + g, rrB = row0 + g + 8;
    const int f    = f0 + sub;

    uint32_t* XHs  = XH + sub * 2304;
    uint32_t* XLs  = XL + sub * 2304;
    uint32_t* KTHs = KTH + sub * 1280;
    uint32_t* KTLs = KTL + sub * 1280;
    uint32_t* VTHs = VTH + sub * 1152;
    uint32_t* VTLs = VTL + sub * 1152;

    // Stage x slices for both f's
    for (int i = tid; i < 2 * 64 * 32; i += 256) {
        int s = i >> 11, rem = i & 2047, row = rem >> 5, dp = rem & 31;
        const float* xp = x + ((size_t)(b * TT + row) * FF + (f0 + s)) * DD;
        float2 v = *(const float2*)(xp + 2 * dp);
        split_pk(v.x, v.y, XH[s * 2304 + row * 36 + dp], XL[s * 2304 + row * 36 + dp]);
    }

    float oacc[8][4];
#pragma unroll
    for (int j = 0; j < 8; j++)
#pragma unroll
        for (int i = 0; i < 4; i++) oacc[j][i] = 0.f;

    for (int h = 0; h < HH; h++) {
        __syncthreads();
        {
            const uint4* srcv = wsrc + (size_t)h * 2368;
            uint4* dstv = (uint4*)(smw + 9216);
            for (int i = tid; i < 2368; i += 256) dstv[i] = srcv[i];
        }
        __syncthreads();

        // --- GEMM1 ---
        float c12[12][4];
#pragma unroll
        for (int j = 0; j < 12; j++)
#pragma unroll
            for (int i = 0; i < 4; i++) c12[j][i] = 0.f;
        for (int kk = 0; kk < 4; kk++) {
            uint32_t ah[4], al[4];
            ldAw(XHs + row0 * 36 + kk * 8, 36, g, t, ah);
            ldAw(XLs + row0 * 36 + kk * 8, 36, g, t, al);
#pragma unroll
            for (int j = 0; j < 12; j++) {
                uint32_t bh2[2], bl2[2];
                ldBw(WCH + j * 8 * 36 + kk * 8, 36, g, t, bh2);
                ldBw(WCL + j * 8 * 36 + kk * 8, 36, g, t, bl2);
                mma3(c12[j], ah, al, bh2, bl2);
            }
        }
        uint32_t QAh[2][4], QAl[2][4];
#pragma unroll
        for (int j = 0; j < 4; j++) {
            int cc = j * 8 + 2 * t;
            float b0 = bq_g[h * 32 + cc], b1 = bq_g[h * 32 + cc + 1];
            float v0 = (c12[j][0] + b0) * QSCALE, v1 = (c12[j][1] + b1) * QSCALE;
            float v2 = (c12[j][2] + b0) * QSCALE, v3 = (c12[j][3] + b1) * QSCALE;
            int kc = j >> 1, e = j & 1;
            split_pk(v0, v1, QAh[kc][2 * e],     QAl[kc][2 * e]);
            split_pk(v2, v3, QAh[kc][2 * e + 1], QAl[kc][2 * e + 1]);
        }
#pragma unroll
        for (int j = 4; j < 8; j++) {
            int cc = (j - 4) * 8 + 2 * t;
            float b0 = bk_g[h * 32 + cc], b1 = bk_g[h * 32 + cc + 1];
            int kp = cc >> 1;
            split_pk(c12[j][0] + b0, c12[j][1] + b1, KTHs[rrA * 20 + kp], KTLs[rrA * 20 + kp]);
            split_pk(c12[j][2] + b0, c12[j][3] + b1, KTHs[rrB * 20 + kp], KTLs[rrB * 20 + kp]);
        }
        {
            __nv_bfloat16* vh = reinterpret_cast<__nv_bfloat16*>(VTHs);
            __nv_bfloat16* vl = reinterpret_cast<__nv_bfloat16*>(VTLs);
#pragma unroll
            for (int j = 8; j < 12; j++) {
                int vk = (j - 8) * 8 + 2 * t;
                float b0 = bv_g[h * 32 + vk], b1 = bv_g[h * 32 + vk + 1];
                float vv[4] = {c12[j][0] + b0, c12[j][1] + b1, c12[j][2] + b0, c12[j][3] + b1};
                int   cl[4] = {vk, vk + 1, vk, vk + 1};
                int   rw[4] = {rrA, rrA, rrB, rrB};
#pragma unroll
                for (int q2 = 0; q2 < 4; q2++) {
                    __nv_bfloat16 hb = __float2bfloat16(vv[q2]);
                    float lf = vv[q2] - __bfloat162float(hb);
                    vh[cl[q2] * 72 + rw[q2]] = hb;
                    vl[cl[q2] * 72 + rw[q2]] = __float2bfloat16(lf);
                }
            }
        }
        __syncthreads();

        // --- S = Q K^T over 64 cols, full-row softmax ---
        float cS[8][4];
#pragma unroll
        for (int j = 0; j < 8; j++)
#pragma unroll
            for (int i = 0; i < 4; i++) cS[j][i] = 0.f;
#pragma unroll
        for (int kk = 0; kk < 2; kk++) {
#pragma unroll
            for (int j = 0; j < 8; j++) {
                uint32_t bh2[2], bl2[2];
                ldBw(KTHs + j * 8 * 20 + kk * 8, 20, g, t, bh2);
                ldBw(KTLs + j * 8 * 20 + kk * 8, 20, g, t, bl2);
                mma3(cS[j], QAh[kk], QAl[kk], bh2, bl2);
            }
        }
        float mA = cS[0][0], mB = cS[0][2];
#pragma unroll
        for (int j = 0; j < 8; j++) {
            mA = fmaxf(mA, fmaxf(cS[j][0], cS[j][1]));
            mB = fmaxf(mB, fmaxf(cS[j][2], cS[j][3]));
        }
        mA = fmaxf(mA, __shfl_xor_sync(0xffffffff, mA, 1));
        mA = fmaxf(mA, __shfl_xor_sync(0xffffffff, mA, 2));
        mB = fmaxf(mB, __shfl_xor_sync(0xffffffff, mB, 1));
        mB = fmaxf(mB, __shfl_xor_sync(0xffffffff, mB, 2));
        float sA = 0.f, sB = 0.f;
#pragma unroll
        for (int j = 0; j < 8; j++) {
            cS[j][0] = ex2f(cS[j][0] - mA); sA += cS[j][0];
            cS[j][1] = ex2f(cS[j][1] - mA); sA += cS[j][1];
            cS[j][2] = ex2f(cS[j][2] - mB); sB += cS[j][2];
            cS[j][3] = ex2f(cS[j][3] - mB); sB += cS[j][3];
        }
        sA += __shfl_xor_sync(0xffffffff, sA, 1);
        sA += __shfl_xor_sync(0xffffffff, sA, 2);
        sB += __shfl_xor_sync(0xffffffff, sB, 1);
        sB += __shfl_xor_sync(0xffffffff, sB, 2);
        float invA = __fdividef(1.f, sA), invB = __fdividef(1.f, sB);

        // P -> regs (A-frags for PV)
        uint32_t PAh[4][4], PAl[4][4];
#pragma unroll
        for (int kc = 0; kc < 4; kc++) {
            int j0 = 2 * kc;
            split_pk(cS[j0][0] * invA,     cS[j0][1] * invA,     PAh[kc][0], PAl[kc][0]);
            split_pk(cS[j0][2] * invB,     cS[j0][3] * invB,     PAh[kc][1], PAl[kc][1]);
            split_pk(cS[j0 + 1][0] * invA, cS[j0 + 1][1] * invA, PAh[kc][2], PAl[kc][2]);
            split_pk(cS[j0 + 1][2] * invB, cS[j0 + 1][3] * invB, PAh[kc][3], PAl[kc][3]);
        }

        // --- PV ---
        float cP[4][4];
#pragma unroll
        for (int j = 0; j < 4; j++)
#pragma unroll
            for (int i = 0; i < 4; i++) cP[j][i] = 0.f;
#pragma unroll
        for (int kk = 0; kk < 4; kk++) {
#pragma unroll
            for (int j = 0; j < 4; j++) {
                uint32_t bh2[2], bl2[2];
                ldBw(VTHs + j * 8 * 36 + kk * 8, 36, g, t, bh2);
                ldBw(VTLs + j * 8 * 36 + kk * 8, 36, g, t, bl2);
                mma3(cP[j], PAh[kk], PAl[kk], bh2, bl2);
            }
        }

        // O -> regs, outproj accumulate
        uint32_t OAh[2][4], OAl[2][4];
#pragma unroll
        for (int j = 0; j < 4; j++) {
            int kc = j >> 1, e = j & 1;
            split_pk(cP[j][0], cP[j][1], OAh[kc][2 * e],     OAl[kc][2 * e]);
            split_pk(cP[j][2], cP[j][3], OAh[kc][2 * e + 1], OAl[kc][2 * e + 1]);
        }
#pragma unroll
        for (int kk = 0; kk < 2; kk++) {
#pragma unroll
            for (int j = 0; j < 8; j++) {
                uint32_t bh2[2], bl2[2];
                ldBw(WOH + j * 8 * 20 + kk * 8, 20, g, t, bh2);
                ldBw(WOL + j * 8 * 20 + kk * 8, 20, g, t, bl2);
                mma3(oacc[j], OAh[kk], OAl[kk], bh2, bl2);
            }
        }
    }

    // Deposit into out (zero-initialized by memset). rows = t, cols = d
#pragma unroll
    for (int j = 0; j < 8; j++) {
        int d0 = j * 8 + 2 * t;
        float bo0 = bo_g[d0], bo1 = bo_g[d0 + 1];
        size_t base0 = ((size_t)(b * TT + rrA) * FF + f) * DD;
        size_t base1 = ((size_t)(b * TT + rrB) * FF + f) * DD;
        atomicAdd(out + base0 + d0,     oacc[j][0] + bo0);
        atomicAdd(out + base0 + d0 + 1, oacc[j][1] + bo1);
        atomicAdd(out + base1 + d0,     oacc[j][2] + bo0);
        atomicAdd(out + base1 + d0 + 1, oacc[j][3] + bo1);
    }
}

// ---------------------------------------------------------------------------
// Fused kernel: even blocks -> temporal, odd blocks -> feature (interleaved).
// out accumulated via commutative float atomicAdds onto zeroed buffer.
// ---------------------------------------------------------------------------
__global__ __launch_bounds__(256, 2) void fused_kernel(
    const float* __restrict__ x,
    const float* __restrict__ tqb, const float* __restrict__ tkb,
    const float* __restrict__ tvb, const float* __restrict__ tob,
    const float* __restrict__ fqb, const float* __restrict__ fkb,
    const float* __restrict__ fvb, const float* __restrict__ fob,
    float* __restrict__ out)
{
    extern __shared__ uint32_t smw[];
    int id = blockIdx.x >> 1;
    if ((blockIdx.x & 1) == 0) {
        temporal_body(smw, id, x, &g_w[0][0][0], tqb, tkb, tvb, tob, out);
    } else {
        feature_body(smw, id, x, &g_w[1][0][0], fqb, fkb, fvb, fob, out);
    }
}

extern "C" void kernel_launch(void* const* d_in, const int* in_sizes, int n_in,
                              void* d_out, int out_size)
{
    const float* x = (const float*)d_in[0];
    const float *tqw, *tqb, *tkw, *tkb, *tvw, *tvb, *tow, *tob;
    const float *fqw, *fqb, *fkw, *fkb, *fvw, *fvb, *fow, *fob;

    if (in_sizes[8] == 64) {  // reference-signature order
        tqw = (const float*)d_in[1];  tqb = (const float*)d_in[2];
        tkw = (const float*)d_in[3];  tkb = (const float*)d_in[4];
        tvw = (const float*)d_in[5];  tvb = (const float*)d_in[6];
        tow = (const float*)d_in[7];  tob = (const float*)d_in[8];
        fqw = (const float*)d_in[9];  fqb = (const float*)d_in[10];
        fkw = (const float*)d_in[11]; fkb = (const float*)d_in[12];
        fvw = (const float*)d_in[13]; fvb = (const float*)d_in[14];
        fow = (const float*)d_in[15]; fob = (const float*)d_in[16];
    } else {                  // setup_inputs dict order
        tqw = (const float*)d_in[1];  tqb = (const float*)d_in[2];
        tkw = (const float*)d_in[3];  tkb = (const float*)d_in[4];
        tvw = (const float*)d_in[5];  tvb = (const float*)d_in[6];
        fqw = (const float*)d_in[7];  fqb = (const float*)d_in[8];
        fkw = (const float*)d_in[9];  fkb = (const float*)d_in[10];
        fvw = (const float*)d_in[11]; fvb = (const float*)d_in[12];
        tow = (const float*)d_in[13]; tob = (const float*)d_in[14];
        fow = (const float*)d_in[15]; fob = (const float*)d_in[16];
    }

    const int SMEM = 28416 * 4;     // 113664 B -> 2 CTA/SM
    cudaFuncSetAttribute(fused_kernel,
                         cudaFuncAttributeMaxDynamicSharedMemorySize, SMEM);

    cudaMemsetAsync(d_out, 0, (size_t)out_size * sizeof(float), 0);
    prep_kernel<<<8, 256>>>(tqw, tkw, tvw, tow, fqw, fkw, fvw, fow);
    fused_kernel<<<4096, 256, SMEM>>>(
        x, tqb, tkb, tvb, tob, fqb, fkb, fvb, fob, (float*)d_out);
}

// round 12
// speedup vs baseline: 1.4113x; 1.0368x over previous
#include <cuda_runtime.h>
#include <cuda_bf16.h>
#include <math.h>
#include <stdint.h>

#define BB 32
#define TT 64
#define FF 128
#define DD 64
#define HH 4
#define KK 32
// (1/sqrt(32)) * log2(e): softmax in log2 domain with ex2
#define QSCALE (0.17677669529663687f * 1.4426950408889634f)

// Pre-split weight buffer: [side][head][9472 words as uint4]
// words layout per head: [0,3456) WCH | [3456,6912) WCL | [6912,8192) WOH | [8192,9472) WOL
__device__ uint4 g_w[2][4][2368];

__device__ __forceinline__ float ex2f(float x) {
    float y;
    asm("ex2.approx.ftz.f32 %0, %1;" : "=f"(y) : "f"(x));
    return y;
}

// Split two fp32 into packed bf16 hi-pair and lo-pair (v ~= hi + lo, err ~2^-18).
__device__ __forceinline__ void split_pk(float v0, float v1, uint32_t& hi, uint32_t& lo) {
    uint32_t h;
    asm("cvt.rn.bf16x2.f32 %0, %1, %2;" : "=r"(h) : "f"(v1), "f"(v0));
    float h0f = __uint_as_float(h << 16);
    float h1f = __uint_as_float(h & 0xffff0000u);
    float l0 = v0 - h0f;
    float l1 = v1 - h1f;
    uint32_t l;
    asm("cvt.rn.bf16x2.f32 %0, %1, %2;" : "=r"(l) : "f"(l1), "f"(l0));
    hi = h;
    lo = l;
}

// m16n8k16 bf16 mma, C += A*B (fp32 accum).
__device__ __forceinline__ void mmabf(float* c, const uint32_t* a, const uint32_t* b) {
    asm volatile(
        "mma.sync.aligned.m16n8k16.row.col.f32.bf16.bf16.f32 "
        "{%0,%1,%2,%3}, {%4,%5,%6,%7}, {%8,%9}, {%0,%1,%2,%3};"
        : "+f"(c[0]), "+f"(c[1]), "+f"(c[2]), "+f"(c[3])
        : "r"(a[0]), "r"(a[1]), "r"(a[2]), "r"(a[3]), "r"(b[0]), "r"(b[1]));
}
// 3-term compensated product: C += (Ah+Al)*(Bh+Bl), dropping Al*Bl.
__device__ __forceinline__ void mma3(float* c, const uint32_t* ah, const uint32_t* al,
                                     const uint32_t* bh, const uint32_t* bl) {
    mmabf(c, al, bh);
    mmabf(c, ah, bl);
    mmabf(c, ah, bh);
}

// ldmatrix.x4: 4 8x8 b16 matrices; lanes 0-7/8-15/16-23/24-31 address m0..m3 rows.
__device__ __forceinline__ void ldsm4(uint32_t addr, uint32_t* r) {
    asm volatile("ldmatrix.sync.aligned.m8n8.x4.shared.b16 {%0,%1,%2,%3}, [%4];"
        : "=r"(r[0]), "=r"(r[1]), "=r"(r[2]), "=r"(r[3])
        : "r"(addr));
}

// B hi+lo fragment pair via one LDSM.x4.
// base = shared byte addr of hi region; lodelta = byte delta to lo region;
// W in words; off_w = n0*W + kk*8 (word offset of the tile).
__device__ __forceinline__ void ldB4(uint32_t base, uint32_t lodelta, int W, int off_w,
                                     int lane, uint32_t* bh, uint32_t* bl) {
    uint32_t a = base + (uint32_t)off_w * 4u
               + (uint32_t)(lane & 7) * (uint32_t)(W * 4)
               + (uint32_t)((lane >> 3) & 1) * 16u
               + (uint32_t)((lane >> 4) & 1) * lodelta;
    uint32_t r[4];
    ldsm4(a, r);
    bh[0] = r[0]; bh[1] = r[1]; bl[0] = r[2]; bl[1] = r[3];
}

// A fragment (one array) via one LDSM.x4: a0=(g,+0) a1=(g+8,+0) a2=(g,+16B) a3=(g+8,+16B).
__device__ __forceinline__ void ldA4(uint32_t base, int W, int off_w, int lane, uint32_t* a) {
    uint32_t ad = base + (uint32_t)off_w * 4u
                + (uint32_t)((lane & 7) + ((lane >> 3) & 1) * 8) * (uint32_t)(W * 4)
                + (uint32_t)((lane >> 4) & 1) * 16u;
    ldsm4(ad, a);
}

// ---------------------------------------------------------------------------
// Prep kernel: split all weights once into g_w (smem-staging layout).
// grid = 8 blocks: block = (side<<2)|head.
// ---------------------------------------------------------------------------
__global__ void prep_kernel(
    const float* __restrict__ tqw, const float* __restrict__ tkw,
    const float* __restrict__ tvw, const float* __restrict__ tow,
    const float* __restrict__ fqw, const float* __restrict__ fkw,
    const float* __restrict__ fvw, const float* __restrict__ fow)
{
    int side = blockIdx.x >> 2, h = blockIdx.x & 3;
    const float* wq = side ? fqw : tqw;
    const float* wk = side ? fkw : tkw;
    const float* wv = side ? fvw : tvw;
    const float* wo = side ? fow : tow;
    uint32_t* dstw = (uint32_t*)&g_w[side][h][0];
    int tid = threadIdx.x;
    for (int i = tid; i < 96 * 32; i += 256) {
        int n = i % 96, dp = i / 96;
        const float* src = (n < 32) ? wq : (n < 64) ? wk : wv;
        int nn = n & 31;
        float v0 = src[(2 * dp) * 128 + h * 32 + nn];
        float v1 = src[(2 * dp + 1) * 128 + h * 32 + nn];
        split_pk(v0, v1, dstw[n * 36 + dp], dstw[3456 + n * 36 + dp]);
    }
    for (int i = tid; i < 64 * 16; i += 256) {
        int d = i & 63, kp = i >> 6;
        float v0 = wo[h * 2048 + (2 * kp) * 64 + d];
        float v1 = wo[h * 2048 + (2 * kp + 1) * 64 + d];
        split_pk(v0, v1, dstw[6912 + d * 20 + kp], dstw[8192 + d * 20 + kp]);
    }
}

// ---------------------------------------------------------------------------
// Feature body: id -> (b, t). 128 rows, 8 warps x 16 rows. atomicAdd into out.
// ---------------------------------------------------------------------------
__device__ __forceinline__ void feature_body(
    uint32_t* smw, int id,
    const float* __restrict__ x,
    const uint4* __restrict__ wsrc,     // &g_w[1][0][0]
    const float* __restrict__ bq_g, const float* __restrict__ bk_g,
    const float* __restrict__ bv_g, const float* __restrict__ bo_g,
    float* __restrict__ out)
{
    uint32_t* XH  = smw;            // 128 x 36
    uint32_t* XL  = smw + 4608;
    uint32_t* KTH = smw + 18688;    // 128 x 20
    uint32_t* KTL = smw + 21248;
    uint32_t* VTH = smw + 23808;    // 32 x 68
    uint32_t* VTL = smw + 25984;    // -> 28160

    const uint32_t sb = (uint32_t)__cvta_generic_to_shared(smw);
    const uint32_t XHb = sb;                    // XL delta = 18432 B
    const uint32_t WCb = sb + 9216u * 4u;       // lo delta = 13824 B
    const uint32_t WOb = sb + 16128u * 4u;      // lo delta = 5120 B
    const uint32_t KTb = sb + 18688u * 4u;      // lo delta = 10240 B
    const uint32_t VTb = sb + 23808u * 4u;      // lo delta = 8704 B

    const int tid  = threadIdx.x;
    const int lane = tid & 31;
    const int w    = tid >> 5;
    const int g    = lane >> 2;
    const int t    = lane & 3;
    const int b    = id >> 6;
    const int tt   = id & 63;
    const int row0 = w * 16;
    const int rrA  = row0 + g, rrB = row0 + g + 8;

    // Stage x slice (contiguous [128][64])
    {
        const float* xp = x + (size_t)(b * TT + tt) * (FF * DD);
        for (int i = tid; i < FF * 32; i += 256) {
            int row = i >> 5, dp = i & 31;
            float2 v = *(const float2*)(xp + row * 64 + 2 * dp);
            split_pk(v.x, v.y, XH[row * 36 + dp], XL[row * 36 + dp]);
        }
    }

    float oacc[8][4];
#pragma unroll
    for (int j = 0; j < 8; j++)
#pragma unroll
        for (int i = 0; i < 4; i++) oacc[j][i] = 0.f;

    for (int h = 0; h < HH; h++) {
        __syncthreads();
        // Stage pre-split weights: straight vector copy into WCH..WOL
        {
            const uint4* srcv = wsrc + (size_t)h * 2368;
            uint4* dstv = (uint4*)(smw + 9216);
            for (int i = tid; i < 2368; i += 256) dstv[i] = srcv[i];
        }
        __syncthreads();

        // --- GEMM1: [16 rows] x [k=64] x [n=96] ---
        float c12[12][4];
#pragma unroll
        for (int j = 0; j < 12; j++)
#pragma unroll
            for (int i = 0; i < 4; i++) c12[j][i] = 0.f;
        for (int kk = 0; kk < 4; kk++) {
            uint32_t ah[4], al[4];
            ldA4(XHb, 36, row0 * 36 + kk * 8, lane, ah);
            ldA4(XHb + 18432u, 36, row0 * 36 + kk * 8, lane, al);
#pragma unroll
            for (int j = 0; j < 12; j++) {
                uint32_t bh2[2], bl2[2];
                ldB4(WCb, 13824u, 36, j * 8 * 36 + kk * 8, lane, bh2, bl2);
                mma3(c12[j], ah, al, bh2, bl2);
            }
        }
        // Epilogue: Q -> regs, K -> smem, V -> smem transposed
        uint32_t QAh[2][4], QAl[2][4];
#pragma unroll
        for (int j = 0; j < 4; j++) {
            int cc = j * 8 + 2 * t;
            float b0 = bq_g[h * 32 + cc], b1 = bq_g[h * 32 + cc + 1];
            float v0 = (c12[j][0] + b0) * QSCALE, v1 = (c12[j][1] + b1) * QSCALE;
            float v2 = (c12[j][2] + b0) * QSCALE, v3 = (c12[j][3] + b1) * QSCALE;
            int kc = j >> 1, e = j & 1;
            split_pk(v0, v1, QAh[kc][2 * e],     QAl[kc][2 * e]);
            split_pk(v2, v3, QAh[kc][2 * e + 1], QAl[kc][2 * e + 1]);
        }
#pragma unroll
        for (int j = 4; j < 8; j++) {
            int cc = (j - 4) * 8 + 2 * t;
            float b0 = bk_g[h * 32 + cc], b1 = bk_g[h * 32 + cc + 1];
            int kp = cc >> 1;
            split_pk(c12[j][0] + b0, c12[j][1] + b1, KTH[rrA * 20 + kp], KTL[rrA * 20 + kp]);
            split_pk(c12[j][2] + b0, c12[j][3] + b1, KTH[rrB * 20 + kp], KTL[rrB * 20 + kp]);
        }
        {
            __nv_bfloat16* vh = reinterpret_cast<__nv_bfloat16*>(VTH);
            __nv_bfloat16* vl = reinterpret_cast<__nv_bfloat16*>(VTL);
#pragma unroll
            for (int j = 8; j < 12; j++) {
                int vk = (j - 8) * 8 + 2 * t;
                float b0 = bv_g[h * 32 + vk], b1 = bv_g[h * 32 + vk + 1];
                float vv[4] = {c12[j][0] + b0, c12[j][1] + b1, c12[j][2] + b0, c12[j][3] + b1};
                int   cl[4] = {vk, vk + 1, vk, vk + 1};
                int   rw[4] = {rrA, rrA, rrB, rrB};
#pragma unroll
                for (int q2 = 0; q2 < 4; q2++) {
                    __nv_bfloat16 hb = __float2bfloat16(vv[q2]);
                    float lf = vv[q2] - __bfloat162float(hb);
                    vh[cl[q2] * 136 + rw[q2]] = hb;
                    vl[cl[q2] * 136 + rw[q2]] = __float2bfloat16(lf);
                }
            }
        }
        __syncthreads();

        // --- S = Q K^T with online softmax, fused PV. 4 chunks of 32 cols ---
        float cP[4][4];
#pragma unroll
        for (int j = 0; j < 4; j++)
#pragma unroll
            for (int i = 0; i < 4; i++) cP[j][i] = 0.f;
        float mrA = -1e30f, mrB = -1e30f, sA = 0.f, sB = 0.f;

        for (int c = 0; c < 4; c++) {
            float cS[4][4];
#pragma unroll
            for (int j = 0; j < 4; j++)
#pragma unroll
                for (int i = 0; i < 4; i++) cS[j][i] = 0.f;
#pragma unroll
            for (int kk = 0; kk < 2; kk++) {
#pragma unroll
                for (int j = 0; j < 4; j++) {
                    uint32_t bh2[2], bl2[2];
                    ldB4(KTb, 10240u, 20, (c * 4 + j) * 8 * 20 + kk * 8, lane, bh2, bl2);
                    mma3(cS[j], QAh[kk], QAl[kk], bh2, bl2);
                }
            }
            float mA = cS[0][0], mB = cS[0][2];
#pragma unroll
            for (int j = 0; j < 4; j++) {
                mA = fmaxf(mA, fmaxf(cS[j][0], cS[j][1]));
                mB = fmaxf(mB, fmaxf(cS[j][2], cS[j][3]));
            }
            mA = fmaxf(mA, __shfl_xor_sync(0xffffffff, mA, 1));
            mA = fmaxf(mA, __shfl_xor_sync(0xffffffff, mA, 2));
            mB = fmaxf(mB, __shfl_xor_sync(0xffffffff, mB, 1));
            mB = fmaxf(mB, __shfl_xor_sync(0xffffffff, mB, 2));
            float nmA = fmaxf(mrA, mA), nmB = fmaxf(mrB, mB);
            float scA = ex2f(mrA - nmA), scB = ex2f(mrB - nmB);
            float chA = 0.f, chB = 0.f;
#pragma unroll
            for (int j = 0; j < 4; j++) {
                cS[j][0] = ex2f(cS[j][0] - nmA); chA += cS[j][0];
                cS[j][1] = ex2f(cS[j][1] - nmA); chA += cS[j][1];
                cS[j][2] = ex2f(cS[j][2] - nmB); chB += cS[j][2];
                cS[j][3] = ex2f(cS[j][3] - nmB); chB += cS[j][3];
            }
            sA = sA * scA + chA;
            sB = sB * scB + chB;
#pragma unroll
            for (int j = 0; j < 4; j++) {
                cP[j][0] *= scA; cP[j][1] *= scA;
                cP[j][2] *= scB; cP[j][3] *= scB;
            }
            uint32_t ph[2][4], pl[2][4];
#pragma unroll
            for (int k0e = 0; k0e < 2; k0e++) {
                int j0 = 2 * k0e;
                split_pk(cS[j0][0],     cS[j0][1],     ph[k0e][0], pl[k0e][0]);
                split_pk(cS[j0][2],     cS[j0][3],     ph[k0e][1], pl[k0e][1]);
                split_pk(cS[j0 + 1][0], cS[j0 + 1][1], ph[k0e][2], pl[k0e][2]);
                split_pk(cS[j0 + 1][2], cS[j0 + 1][3], ph[k0e][3], pl[k0e][3]);
            }
#pragma unroll
            for (int k0e = 0; k0e < 2; k0e++) {
                int kkv = 2 * c + k0e;
#pragma unroll
                for (int j = 0; j < 4; j++) {
                    uint32_t bh2[2], bl2[2];
                    ldB4(VTb, 8704u, 68, j * 8 * 68 + kkv * 8, lane, bh2, bl2);
                    mma3(cP[j], ph[k0e], pl[k0e], bh2, bl2);
                }
            }
            mrA = nmA; mrB = nmB;
        }
        sA += __shfl_xor_sync(0xffffffff, sA, 1);
        sA += __shfl_xor_sync(0xffffffff, sA, 2);
        sB += __shfl_xor_sync(0xffffffff, sB, 1);
        sB += __shfl_xor_sync(0xffffffff, sB, 2);
        float invA = __fdividef(1.f, sA), invB = __fdividef(1.f, sB);
#pragma unroll
        for (int j = 0; j < 4; j++) {
            cP[j][0] *= invA; cP[j][1] *= invA;
            cP[j][2] *= invB; cP[j][3] *= invB;
        }

        // O -> regs, outproj accumulate
        uint32_t OAh[2][4], OAl[2][4];
#pragma unroll
        for (int j = 0; j < 4; j++) {
            int kc = j >> 1, e = j & 1;
            split_pk(cP[j][0], cP[j][1], OAh[kc][2 * e],     OAl[kc][2 * e]);
            split_pk(cP[j][2], cP[j][3], OAh[kc][2 * e + 1], OAl[kc][2 * e + 1]);
        }
#pragma unroll
        for (int kk = 0; kk < 2; kk++) {
#pragma unroll
            for (int j = 0; j < 8; j++) {
                uint32_t bh2[2], bl2[2];
                ldB4(WOb, 5120u, 20, j * 8 * 20 + kk * 8, lane, bh2, bl2);
                mma3(oacc[j], OAh[kk], OAl[kk], bh2, bl2);
            }
        }
    }

    // Deposit into out (zero-initialized by memset). rows = f, cols = d
#pragma unroll
    for (int j = 0; j < 8; j++) {
        int d0 = j * 8 + 2 * t;
        float bo0 = bo_g[d0], bo1 = bo_g[d0 + 1];
        size_t base0 = ((size_t)(b * TT + tt) * FF + rrA) * DD;
        size_t base1 = ((size_t)(b * TT + tt) * FF + rrB) * DD;
        atomicAdd(out + base0 + d0,     oacc[j][0] + bo0);
        atomicAdd(out + base0 + d0 + 1, oacc[j][1] + bo1);
        atomicAdd(out + base1 + d0,     oacc[j][2] + bo0);
        atomicAdd(out + base1 + d0 + 1, oacc[j][3] + bo1);
    }
}

// ---------------------------------------------------------------------------
// Temporal body: id -> (b, f-pair). 2 sub-blocks x 64 rows (T). atomicAdd out.
// ---------------------------------------------------------------------------
__device__ __forceinline__ void temporal_body(
    uint32_t* smw, int id,
    const float* __restrict__ x,
    const uint4* __restrict__ wsrc,     // &g_w[0][0][0]
    const float* __restrict__ bq_g, const float* __restrict__ bk_g,
    const float* __restrict__ bv_g, const float* __restrict__ bo_g,
    float* __restrict__ out)
{
    uint32_t* XH  = smw;            // 2 x (64 x 36)
    uint32_t* XL  = smw + 4608;
    uint32_t* KTH = smw + 18688;    // 2 x (64 x 20)
    uint32_t* KTL = smw + 21248;
    uint32_t* VTH = smw + 23808;    // 2 x (32 x 36)
    uint32_t* VTL = smw + 26112;    // -> 28416

    const int tid  = threadIdx.x;
    const int lane = tid & 31;
    const int w    = tid >> 5;
    const int g    = lane >> 2;
    const int t    = lane & 3;
    const int b    = id >> 6;
    const int f0   = (id & 63) * 2;
    const int sub  = w >> 2;
    const int row0 = (w & 3) * 16;
    const int rrA  = row0 + g, rrB = row0 + g + 8;
    const int f    = f0 + sub;

    uint32_t* KTHs = KTH + sub * 1280;
    uint32_t* KTLs = KTL + sub * 1280;
    uint32_t* VTHs = VTH + sub * 1152;
    uint32_t* VTLs = VTL + sub * 1152;

    const uint32_t sb  = (uint32_t)__cvta_generic_to_shared(smw);
    const uint32_t XHb = sb + (uint32_t)(sub * 2304) * 4u;   // XL delta = 18432 B
    const uint32_t WCb = sb + 9216u * 4u;                    // lo delta = 13824 B
    const uint32_t WOb = sb + 16128u * 4u;                   // lo delta = 5120 B
    const uint32_t KTb = sb + (18688u + (uint32_t)(sub * 1280)) * 4u;  // lo delta 10240 B
    const uint32_t VTb = sb + (23808u + (uint32_t)(sub * 1152)) * 4u;  // lo delta 9216 B

    // Stage x slices for both f's
    for (int i = tid; i < 2 * 64 * 32; i += 256) {
        int s = i >> 11, rem = i & 2047, row = rem >> 5, dp = rem & 31;
        const float* xp = x + ((size_t)(b * TT + row) * FF + (f0 + s)) * DD;
        float2 v = *(const float2*)(xp + 2 * dp);
        split_pk(v.x, v.y, XH[s * 2304 + row * 36 + dp], XL[s * 2304 + row * 36 + dp]);
    }

    float oacc[8][4];
#pragma unroll
    for (int j = 0; j < 8; j++)
#pragma unroll
        for (int i = 0; i < 4; i++) oacc[j][i] = 0.f;

    for (int h = 0; h < HH; h++) {
        __syncthreads();
        {
            const uint4* srcv = wsrc + (size_t)h * 2368;
            uint4* dstv = (uint4*)(smw + 9216);
            for (int i = tid; i < 2368; i += 256) dstv[i] = srcv[i];
        }
        __syncthreads();

        // --- GEMM1 ---
        float c12[12][4];
#pragma unroll
        for (int j = 0; j < 12; j++)
#pragma unroll
            for (int i = 0; i < 4; i++) c12[j][i] = 0.f;
        for (int kk = 0; kk < 4; kk++) {
            uint32_t ah[4], al[4];
            ldA4(XHb, 36, row0 * 36 + kk * 8, lane, ah);
            ldA4(XHb + 18432u, 36, row0 * 36 + kk * 8, lane, al);
#pragma unroll
            for (int j = 0; j < 12; j++) {
                uint32_t bh2[2], bl2[2];
                ldB4(WCb, 13824u, 36, j * 8 * 36 + kk * 8, lane, bh2, bl2);
                mma3(c12[j], ah, al, bh2, bl2);
            }
        }
        uint32_t QAh[2][4], QAl[2][4];
#pragma unroll
        for (int j = 0; j < 4; j++) {
            int cc = j * 8 + 2 * t;
            float b0 = bq_g[h * 32 + cc], b1 = bq_g[h * 32 + cc + 1];
            float v0 = (c12[j][0] + b0) * QSCALE, v1 = (c12[j][1] + b1) * QSCALE;
            float v2 = (c12[j][2] + b0) * QSCALE, v3 = (c12[j][3] + b1) * QSCALE;
            int kc = j >> 1, e = j & 1;
            split_pk(v0, v1, QAh[kc][2 * e],     QAl[kc][2 * e]);
            split_pk(v2, v3, QAh[kc][2 * e + 1], QAl[kc][2 * e + 1]);
        }
#pragma unroll
        for (int j = 4; j < 8; j++) {
            int cc = (j - 4) * 8 + 2 * t;
            float b0 = bk_g[h * 32 + cc], b1 = bk_g[h * 32 + cc + 1];
            int kp = cc >> 1;
            split_pk(c12[j][0] + b0, c12[j][1] + b1, KTHs[rrA * 20 + kp], KTLs[rrA * 20 + kp]);
            split_pk(c12[j][2] + b0, c12[j][3] + b1, KTHs[rrB * 20 + kp], KTLs[rrB * 20 + kp]);
        }
        {
            __nv_bfloat16* vh = reinterpret_cast<__nv_bfloat16*>(VTHs);
            __nv_bfloat16* vl = reinterpret_cast<__nv_bfloat16*>(VTLs);
#pragma unroll
            for (int j = 8; j < 12; j++) {
                int vk = (j - 8) * 8 + 2 * t;
                float b0 = bv_g[h * 32 + vk], b1 = bv_g[h * 32 + vk + 1];
                float vv[4] = {c12[j][0] + b0, c12[j][1] + b1, c12[j][2] + b0, c12[j][3] + b1};
                int   cl[4] = {vk, vk + 1, vk, vk + 1};
                int   rw[4] = {rrA, rrA, rrB, rrB};
#pragma unroll
                for (int q2 = 0; q2 < 4; q2++) {
                    __nv_bfloat16 hb = __float2bfloat16(vv[q2]);
                    float lf = vv[q2] - __bfloat162float(hb);
                    vh[cl[q2] * 72 + rw[q2]] = hb;
                    vl[cl[q2] * 72 + rw[q2]] = __float2bfloat16(lf);
                }
            }
        }
        __syncthreads();

        // --- S = Q K^T over 64 cols, full-row softmax ---
        float cS[8][4];
#pragma unroll
        for (int j = 0; j < 8; j++)
#pragma unroll
            for (int i = 0; i < 4; i++) cS[j][i] = 0.f;
#pragma unroll
        for (int kk = 0; kk < 2; kk++) {
#pragma unroll
            for (int j = 0; j < 8; j++) {
                uint32_t bh2[2], bl2[2];
                ldB4(KTb, 10240u, 20, j * 8 * 20 + kk * 8, lane, bh2, bl2);
                mma3(cS[j], QAh[kk], QAl[kk], bh2, bl2);
            }
        }
        float mA = cS[0][0], mB = cS[0][2];
#pragma unroll
        for (int j = 0; j < 8; j++) {
            mA = fmaxf(mA, fmaxf(cS[j][0], cS[j][1]));
            mB = fmaxf(mB, fmaxf(cS[j][2], cS[j][3]));
        }
        mA = fmaxf(mA, __shfl_xor_sync(0xffffffff, mA, 1));
        mA = fmaxf(mA, __shfl_xor_sync(0xffffffff, mA, 2));
        mB = fmaxf(mB, __shfl_xor_sync(0xffffffff, mB, 1));
        mB = fmaxf(mB, __shfl_xor_sync(0xffffffff, mB, 2));
        float sA = 0.f, sB = 0.f;
#pragma unroll
        for (int j = 0; j < 8; j++) {
            cS[j][0] = ex2f(cS[j][0] - mA); sA += cS[j][0];
            cS[j][1] = ex2f(cS[j][1] - mA); sA += cS[j][1];
            cS[j][2] = ex2f(cS[j][2] - mB); sB += cS[j][2];
            cS[j][3] = ex2f(cS[j][3] - mB); sB += cS[j][3];
        }
        sA += __shfl_xor_sync(0xffffffff, sA, 1);
        sA += __shfl_xor_sync(0xffffffff, sA, 2);
        sB += __shfl_xor_sync(0xffffffff, sB, 1);
        sB += __shfl_xor_sync(0xffffffff, sB, 2);
        float invA = __fdividef(1.f, sA), invB = __fdividef(1.f, sB);

        // P -> regs (A-frags for PV)
        uint32_t PAh[4][4], PAl[4][4];
#pragma unroll
        for (int kc = 0; kc < 4; kc++) {
            int j0 = 2 * kc;
            split_pk(cS[j0][0] * invA,     cS[j0][1] * invA,     PAh[kc][0], PAl[kc][0]);
            split_pk(cS[j0][2] * invB,     cS[j0][3] * invB,     PAh[kc][1], PAl[kc][1]);
            split_pk(cS[j0 + 1][0] * invA, cS[j0 + 1][1] * invA, PAh[kc][2], PAl[kc][2]);
            split_pk(cS[j0 + 1][2] * invB, cS[j0 + 1][3] * invB, PAh[kc][3], PAl[kc][3]);
        }

        // --- PV ---
        float cP[4][4];
#pragma unroll
        for (int j = 0; j < 4; j++)
#pragma unroll
            for (int i = 0; i < 4; i++) cP[j][i] = 0.f;
#pragma unroll
        for (int kk = 0; kk < 4; kk++) {
#pragma unroll
            for (int j = 0; j < 4; j++) {
                uint32_t bh2[2], bl2[2];
                ldB4(VTb, 9216u, 36, j * 8 * 36 + kk * 8, lane, bh2, bl2);
                mma3(cP[j], PAh[kk], PAl[kk], bh2, bl2);
            }
        }

        // O -> regs, outproj accumulate
        uint32_t OAh[2][4], OAl[2][4];
#pragma unroll
        for (int j = 0; j < 4; j++) {
            int kc = j >> 1, e = j & 1;
            split_pk(cP[j][0], cP[j][1], OAh[kc][2 * e],     OAl[kc][2 * e]);
            split_pk(cP[j][2], cP[j][3], OAh[kc][2 * e + 1], OAl[kc][2 * e + 1]);
        }
#pragma unroll
        for (int kk = 0; kk < 2; kk++) {
#pragma unroll
            for (int j = 0; j < 8; j++) {
                uint32_t bh2[2], bl2[2];
                ldB4(WOb, 5120u, 20, j * 8 * 20 + kk * 8, lane, bh2, bl2);
                mma3(oacc[j], OAh[kk], OAl[kk], bh2, bl2);
            }
        }
    }

    // Deposit into out (zero-initialized by memset). rows = t, cols = d
#pragma unroll
    for (int j = 0; j < 8; j++) {
        int d0 = j * 8 + 2 * t;
        float bo0 = bo_g[d0], bo1 = bo_g[d0 + 1];
        size_t base0 = ((size_t)(b * TT + rrA) * FF + f) * DD;
        size_t base1 = ((size_t)(b * TT + rrB) * FF + f) * DD;
        atomicAdd(out + base0 + d0,     oacc[j][0] + bo0);
        atomicAdd(out + base0 + d0 + 1, oacc[j][1] + bo1);
        atomicAdd(out + base1 + d0,     oacc[j][2] + bo0);
        atomicAdd(out + base1 + d0 + 1, oacc[j][3] + bo1);
    }
}

// ---------------------------------------------------------------------------
// Fused kernel: even blocks -> temporal, odd blocks -> feature (interleaved).
// out accumulated via commutative float atomicAdds onto zeroed buffer.
// ---------------------------------------------------------------------------
__global__ __launch_bounds__(256, 2) void fused_kernel(
    const float* __restrict__ x,
    const float* __restrict__ tqb, const float* __restrict__ tkb,
    const float* __restrict__ tvb, const float* __restrict__ tob,
    const float* __restrict__ fqb, const float* __restrict__ fkb,
    const float* __restrict__ fvb, const float* __restrict__ fob,
    float* __restrict__ out)
{
    extern __shared__ uint32_t smw[];
    int id = blockIdx.x >> 1;
    if ((blockIdx.x & 1) == 0) {
        temporal_body(smw, id, x, &g_w[0][0][0], tqb, tkb, tvb, tob, out);
    } else {
        feature_body(smw, id, x, &g_w[1][0][0], fqb, fkb, fvb, fob, out);
    }
}

extern "C" void kernel_launch(void* const* d_in, const int* in_sizes, int n_in,
                              void* d_out, int out_size)
{
    const float* x = (const float*)d_in[0];
    const float *tqw, *tqb, *tkw, *tkb, *tvw, *tvb, *tow, *tob;
    const float *fqw, *fqb, *fkw, *fkb, *fvw, *fvb, *fow, *fob;

    if (in_sizes[8] == 64) {  // reference-signature order
        tqw = (const float*)d_in[1];  tqb = (const float*)d_in[2];
        tkw = (const float*)d_in[3];  tkb = (const float*)d_in[4];
        tvw = (const float*)d_in[5];  tvb = (const float*)d_in[6];
        tow = (const float*)d_in[7];  tob = (const float*)d_in[8];
        fqw = (const float*)d_in[9];  fqb = (const float*)d_in[10];
        fkw = (const float*)d_in[11]; fkb = (const float*)d_in[12];
        fvw = (const float*)d_in[13]; fvb = (const float*)d_in[14];
        fow = (const float*)d_in[15]; fob = (const float*)d_in[16];
    } else {                  // setup_inputs dict order
        tqw = (const float*)d_in[1];  tqb = (const float*)d_in[2];
        tkw = (const float*)d_in[3];  tkb = (const float*)d_in[4];
        tvw = (const float*)d_in[5];  tvb = (const float*)d_in[6];
        fqw = (const float*)d_in[7];  fqb = (const float*)d_in[8];
        fkw = (const float*)d_in[9];  fkb = (const float*)d_in[10];
        fvw = (const float*)d_in[11]; fvb = (const float*)d_in[12];
        tow = (const float*)d_in[13]; tob = (const float*)d_in[14];
        fow = (const float*)d_in[15]; fob = (const float*)d_in[16];
    }

    const int SMEM = 28416 * 4;     // 113664 B -> 2 CTA/SM
    cudaFuncSetAttribute(fused_kernel,
                         cudaFuncAttributeMaxDynamicSharedMemorySize, SMEM);

    cudaMemsetAsync(d_out, 0, (size_t)out_size * sizeof(float), 0);
    prep_kernel<<<8, 256>>>(tqw, tkw, tvw, tow, fqw, fkw, fvw, fow);
    fused_kernel<<<4096, 256, SMEM>>>(
        x, tqb, tkb, tvb, tob, fqb, fkb, fvb, fob, (float*)d_out);
}

// round 13
// speedup vs baseline: 1.4262x; 1.0106x over previous
#include <cuda_runtime.h>
#include <cuda_bf16.h>
#include <math.h>
#include <stdint.h>

#define BB 32
#define TT 64
#define FF 128
#define DD 64
#define HH 4
#define KK 32
// (1/sqrt(32)) * log2(e): softmax in log2 domain with ex2
#define QSCALE (0.17677669529663687f * 1.4426950408889634f)

// Pre-split weight buffer: [side][head][9472 words as uint4]
// words layout per head: [0,3456) WCH | [3456,6912) WCL | [6912,8192) WOH | [8192,9472) WOL
__device__ uint4 g_w[2][4][2368];

__device__ __forceinline__ float ex2f(float x) {
    float y;
    asm("ex2.approx.ftz.f32 %0, %1;" : "=f"(y) : "f"(x));
    return y;
}

// Split two fp32 into packed bf16 hi-pair and lo-pair (v ~= hi + lo, err ~2^-18).
__device__ __forceinline__ void split_pk(float v0, float v1, uint32_t& hi, uint32_t& lo) {
    uint32_t h;
    asm("cvt.rn.bf16x2.f32 %0, %1, %2;" : "=r"(h) : "f"(v1), "f"(v0));
    float h0f = __uint_as_float(h << 16);
    float h1f = __uint_as_float(h & 0xffff0000u);
    float l0 = v0 - h0f;
    float l1 = v1 - h1f;
    uint32_t l;
    asm("cvt.rn.bf16x2.f32 %0, %1, %2;" : "=r"(l) : "f"(l1), "f"(l0));
    hi = h;
    lo = l;
}

// m16n8k16 bf16 mma, C += A*B (fp32 accum).
__device__ __forceinline__ void mmabf(float* c, const uint32_t* a, const uint32_t* b) {
    asm volatile(
        "mma.sync.aligned.m16n8k16.row.col.f32.bf16.bf16.f32 "
        "{%0,%1,%2,%3}, {%4,%5,%6,%7}, {%8,%9}, {%0,%1,%2,%3};"
        : "+f"(c[0]), "+f"(c[1]), "+f"(c[2]), "+f"(c[3])
        : "r"(a[0]), "r"(a[1]), "r"(a[2]), "r"(a[3]), "r"(b[0]), "r"(b[1]));
}
// 3-term compensated product: C += (Ah+Al)*(Bh+Bl), dropping Al*Bl.
__device__ __forceinline__ void mma3(float* c, const uint32_t* ah, const uint32_t* al,
                                     const uint32_t* bh, const uint32_t* bl) {
    mmabf(c, al, bh);
    mmabf(c, ah, bl);
    mmabf(c, ah, bh);
}

// ldmatrix.x4: 4 8x8 b16 matrices; lanes 0-7/8-15/16-23/24-31 address m0..m3 rows.
__device__ __forceinline__ void ldsm4(uint32_t addr, uint32_t* r) {
    asm volatile("ldmatrix.sync.aligned.m8n8.x4.shared.b16 {%0,%1,%2,%3}, [%4];"
        : "=r"(r[0]), "=r"(r[1]), "=r"(r[2]), "=r"(r[3])
        : "r"(addr));
}

// B hi+lo fragment pair via one LDSM.x4.
__device__ __forceinline__ void ldB4(uint32_t base, uint32_t lodelta, int W, int off_w,
                                     int lane, uint32_t* bh, uint32_t* bl) {
    uint32_t a = base + (uint32_t)off_w * 4u
               + (uint32_t)(lane & 7) * (uint32_t)(W * 4)
               + (uint32_t)((lane >> 3) & 1) * 16u
               + (uint32_t)((lane >> 4) & 1) * lodelta;
    uint32_t r[4];
    ldsm4(a, r);
    bh[0] = r[0]; bh[1] = r[1]; bl[0] = r[2]; bl[1] = r[3];
}

// A fragment via one LDSM.x4: a0=(g,+0) a1=(g+8,+0) a2=(g,+16B) a3=(g+8,+16B).
__device__ __forceinline__ void ldA4(uint32_t base, int W, int off_w, int lane, uint32_t* a) {
    uint32_t ad = base + (uint32_t)off_w * 4u
                + (uint32_t)((lane & 7) + ((lane >> 3) & 1) * 8) * (uint32_t)(W * 4)
                + (uint32_t)((lane >> 4) & 1) * 16u;
    ldsm4(ad, a);
}

// Feature S-chunk mma: 32 cols of S (4 j-tiles x 2 ksteps x mma3).
__device__ __forceinline__ void sfeat_chunk(
    uint32_t KTb, int c, int lane,
    const uint32_t QAh[2][4], const uint32_t QAl[2][4], float cS[4][4])
{
#pragma unroll
    for (int j = 0; j < 4; j++)
#pragma unroll
        for (int i = 0; i < 4; i++) cS[j][i] = 0.f;
#pragma unroll
    for (int kk = 0; kk < 2; kk++) {
#pragma unroll
        for (int j = 0; j < 4; j++) {
            uint32_t bh2[2], bl2[2];
            ldB4(KTb, 10240u, 20, (c * 4 + j) * 8 * 20 + kk * 8, lane, bh2, bl2);
            mma3(cS[j], QAh[kk], QAl[kk], bh2, bl2);
        }
    }
}

// ---------------------------------------------------------------------------
// Prep kernel: split all weights once into g_w (smem-staging layout).
// ---------------------------------------------------------------------------
__global__ void prep_kernel(
    const float* __restrict__ tqw, const float* __restrict__ tkw,
    const float* __restrict__ tvw, const float* __restrict__ tow,
    const float* __restrict__ fqw, const float* __restrict__ fkw,
    const float* __restrict__ fvw, const float* __restrict__ fow)
{
    int side = blockIdx.x >> 2, h = blockIdx.x & 3;
    const float* wq = side ? fqw : tqw;
    const float* wk = side ? fkw : tkw;
    const float* wv = side ? fvw : tvw;
    const float* wo = side ? fow : tow;
    uint32_t* dstw = (uint32_t*)&g_w[side][h][0];
    int tid = threadIdx.x;
    for (int i = tid; i < 96 * 32; i += 256) {
        int n = i % 96, dp = i / 96;
        const float* src = (n < 32) ? wq : (n < 64) ? wk : wv;
        int nn = n & 31;
        float v0 = src[(2 * dp) * 128 + h * 32 + nn];
        float v1 = src[(2 * dp + 1) * 128 + h * 32 + nn];
        split_pk(v0, v1, dstw[n * 36 + dp], dstw[3456 + n * 36 + dp]);
    }
    for (int i = tid; i < 64 * 16; i += 256) {
        int d = i & 63, kp = i >> 6;
        float v0 = wo[h * 2048 + (2 * kp) * 64 + d];
        float v1 = wo[h * 2048 + (2 * kp + 1) * 64 + d];
        split_pk(v0, v1, dstw[6912 + d * 20 + kp], dstw[8192 + d * 20 + kp]);
    }
}

// ---------------------------------------------------------------------------
// Feature body: id -> (b, t). 128 rows, 8 warps x 16 rows. atomicAdd into out.
// ---------------------------------------------------------------------------
__device__ __forceinline__ void feature_body(
    uint32_t* smw, int id,
    const float* __restrict__ x,
    const uint4* __restrict__ wsrc,
    const float* __restrict__ bq_g, const float* __restrict__ bk_g,
    const float* __restrict__ bv_g, const float* __restrict__ bo_g,
    float* __restrict__ out)
{
    uint32_t* XH  = smw;            // 128 x 36
    uint32_t* XL  = smw + 4608;
    uint32_t* KTH = smw + 18688;    // 128 x 20
    uint32_t* KTL = smw + 21248;
    uint32_t* VTH = smw + 23808;    // 32 x 68
    uint32_t* VTL = smw + 25984;    // -> 28160

    const uint32_t sb = (uint32_t)__cvta_generic_to_shared(smw);
    const uint32_t XHb = sb;                    // XL delta = 18432 B
    const uint32_t WCb = sb + 9216u * 4u;       // lo delta = 13824 B
    const uint32_t WOb = sb + 16128u * 4u;      // lo delta = 5120 B
    const uint32_t KTb = sb + 18688u * 4u;      // lo delta = 10240 B
    const uint32_t VTb = sb + 23808u * 4u;      // lo delta = 8704 B

    const int tid  = threadIdx.x;
    const int lane = tid & 31;
    const int w    = tid >> 5;
    const int g    = lane >> 2;
    const int t    = lane & 3;
    const int b    = id >> 6;
    const int tt   = id & 63;
    const int row0 = w * 16;
    const int rrA  = row0 + g, rrB = row0 + g + 8;

    // Stage x slice (contiguous [128][64])
    {
        const float* xp = x + (size_t)(b * TT + tt) * (FF * DD);
        for (int i = tid; i < FF * 32; i += 256) {
            int row = i >> 5, dp = i & 31;
            float2 v = *(const float2*)(xp + row * 64 + 2 * dp);
            split_pk(v.x, v.y, XH[row * 36 + dp], XL[row * 36 + dp]);
        }
    }

    float oacc[8][4];
#pragma unroll
    for (int j = 0; j < 8; j++)
#pragma unroll
        for (int i = 0; i < 4; i++) oacc[j][i] = 0.f;

    for (int h = 0; h < HH; h++) {
        __syncthreads();
        // Stage pre-split weights: straight vector copy into WCH..WOL
        {
            const uint4* srcv = wsrc + (size_t)h * 2368;
            uint4* dstv = (uint4*)(smw + 9216);
            for (int i = tid; i < 2368; i += 256) dstv[i] = srcv[i];
        }
        __syncthreads();

        // --- GEMM1: [16 rows] x [k=64] x [n=96] ---
        float c12[12][4];
#pragma unroll
        for (int j = 0; j < 12; j++)
#pragma unroll
            for (int i = 0; i < 4; i++) c12[j][i] = 0.f;
        for (int kk = 0; kk < 4; kk++) {
            uint32_t ah[4], al[4];
            ldA4(XHb, 36, row0 * 36 + kk * 8, lane, ah);
            ldA4(XHb + 18432u, 36, row0 * 36 + kk * 8, lane, al);
#pragma unroll
            for (int j = 0; j < 12; j++) {
                uint32_t bh2[2], bl2[2];
                ldB4(WCb, 13824u, 36, j * 8 * 36 + kk * 8, lane, bh2, bl2);
                mma3(c12[j], ah, al, bh2, bl2);
            }
        }
        // Epilogue: Q -> regs, K -> smem, V -> smem transposed
        uint32_t QAh[2][4], QAl[2][4];
#pragma unroll
        for (int j = 0; j < 4; j++) {
            int cc = j * 8 + 2 * t;
            float b0 = bq_g[h * 32 + cc], b1 = bq_g[h * 32 + cc + 1];
            float v0 = (c12[j][0] + b0) * QSCALE, v1 = (c12[j][1] + b1) * QSCALE;
            float v2 = (c12[j][2] + b0) * QSCALE, v3 = (c12[j][3] + b1) * QSCALE;
            int kc = j >> 1, e = j & 1;
            split_pk(v0, v1, QAh[kc][2 * e],     QAl[kc][2 * e]);
            split_pk(v2, v3, QAh[kc][2 * e + 1], QAl[kc][2 * e + 1]);
        }
#pragma unroll
        for (int j = 4; j < 8; j++) {
            int cc = (j - 4) * 8 + 2 * t;
            float b0 = bk_g[h * 32 + cc], b1 = bk_g[h * 32 + cc + 1];
            int kp = cc >> 1;
            split_pk(c12[j][0] + b0, c12[j][1] + b1, KTH[rrA * 20 + kp], KTL[rrA * 20 + kp]);
            split_pk(c12[j][2] + b0, c12[j][3] + b1, KTH[rrB * 20 + kp], KTL[rrB * 20 + kp]);
        }
        {
            __nv_bfloat16* vh = reinterpret_cast<__nv_bfloat16*>(VTH);
            __nv_bfloat16* vl = reinterpret_cast<__nv_bfloat16*>(VTL);
#pragma unroll
            for (int j = 8; j < 12; j++) {
                int vk = (j - 8) * 8 + 2 * t;
                float b0 = bv_g[h * 32 + vk], b1 = bv_g[h * 32 + vk + 1];
                float vv[4] = {c12[j][0] + b0, c12[j][1] + b1, c12[j][2] + b0, c12[j][3] + b1};
                int   cl[4] = {vk, vk + 1, vk, vk + 1};
                int   rw[4] = {rrA, rrA, rrB, rrB};
#pragma unroll
                for (int q2 = 0; q2 < 4; q2++) {
                    __nv_bfloat16 hb = __float2bfloat16(vv[q2]);
                    float lf = vv[q2] - __bfloat162float(hb);
                    vh[cl[q2] * 136 + rw[q2]] = hb;
                    vl[cl[q2] * 136 + rw[q2]] = __float2bfloat16(lf);
                }
            }
        }
        __syncthreads();

        // --- S = Q K^T, online softmax, fused PV; pipelined over 4 chunks ---
        float cP[4][4];
#pragma unroll
        for (int j = 0; j < 4; j++)
#pragma unroll
            for (int i = 0; i < 4; i++) cP[j][i] = 0.f;
        float mrA, mrB, sA, sB;
        float cSb[2][4][4];

        sfeat_chunk(KTb, 0, lane, QAh, QAl, cSb[0]);
#pragma unroll
        for (int c = 0; c < 4; c++) {
            float (*cS)[4] = cSb[c & 1];
            // issue NEXT chunk's S mmas before this chunk's reductions:
            // independent tensor work hides shuffle/MUFU scoreboard stalls.
            if (c < 3) sfeat_chunk(KTb, c + 1, lane, QAh, QAl, cSb[(c + 1) & 1]);

            float mA = cS[0][0], mB = cS[0][2];
#pragma unroll
            for (int j = 0; j < 4; j++) {
                mA = fmaxf(mA, fmaxf(cS[j][0], cS[j][1]));
                mB = fmaxf(mB, fmaxf(cS[j][2], cS[j][3]));
            }
            mA = fmaxf(mA, __shfl_xor_sync(0xffffffff, mA, 1));
            mA = fmaxf(mA, __shfl_xor_sync(0xffffffff, mA, 2));
            mB = fmaxf(mB, __shfl_xor_sync(0xffffffff, mB, 1));
            mB = fmaxf(mB, __shfl_xor_sync(0xffffffff, mB, 2));
            float nmA, nmB, chA = 0.f, chB = 0.f;
            if (c == 0) {
                nmA = mA; nmB = mB;
#pragma unroll
                for (int j = 0; j < 4; j++) {
                    cS[j][0] = ex2f(cS[j][0] - nmA); chA += cS[j][0];
                    cS[j][1] = ex2f(cS[j][1] - nmA); chA += cS[j][1];
                    cS[j][2] = ex2f(cS[j][2] - nmB); chB += cS[j][2];
                    cS[j][3] = ex2f(cS[j][3] - nmB); chB += cS[j][3];
                }
                sA = chA; sB = chB;
            } else {
                nmA = fmaxf(mrA, mA); nmB = fmaxf(mrB, mB);
                float scA = ex2f(mrA - nmA), scB = ex2f(mrB - nmB);
#pragma unroll
                for (int j = 0; j < 4; j++) {
                    cS[j][0] = ex2f(cS[j][0] - nmA); chA += cS[j][0];
                    cS[j][1] = ex2f(cS[j][1] - nmA); chA += cS[j][1];
                    cS[j][2] = ex2f(cS[j][2] - nmB); chB += cS[j][2];
                    cS[j][3] = ex2f(cS[j][3] - nmB); chB += cS[j][3];
                }
                sA = sA * scA + chA;
                sB = sB * scB + chB;
#pragma unroll
                for (int j = 0; j < 4; j++) {
                    cP[j][0] *= scA; cP[j][1] *= scA;
                    cP[j][2] *= scB; cP[j][3] *= scB;
                }
            }
            uint32_t ph[2][4], pl[2][4];
#pragma unroll
            for (int k0e = 0; k0e < 2; k0e++) {
                int j0 = 2 * k0e;
                split_pk(cS[j0][0],     cS[j0][1],     ph[k0e][0], pl[k0e][0]);
                split_pk(cS[j0][2],     cS[j0][3],     ph[k0e][1], pl[k0e][1]);
                split_pk(cS[j0 + 1][0], cS[j0 + 1][1], ph[k0e][2], pl[k0e][2]);
                split_pk(cS[j0 + 1][2], cS[j0 + 1][3], ph[k0e][3], pl[k0e][3]);
            }
#pragma unroll
            for (int k0e = 0; k0e < 2; k0e++) {
                int kkv = 2 * c + k0e;
#pragma unroll
                for (int j = 0; j < 4; j++) {
                    uint32_t bh2[2], bl2[2];
                    ldB4(VTb, 8704u, 68, j * 8 * 68 + kkv * 8, lane, bh2, bl2);
                    mma3(cP[j], ph[k0e], pl[k0e], bh2, bl2);
                }
            }
            mrA = nmA; mrB = nmB;
        }
        sA += __shfl_xor_sync(0xffffffff, sA, 1);
        sA += __shfl_xor_sync(0xffffffff, sA, 2);
        sB += __shfl_xor_sync(0xffffffff, sB, 1);
        sB += __shfl_xor_sync(0xffffffff, sB, 2);
        float invA = __fdividef(1.f, sA), invB = __fdividef(1.f, sB);
#pragma unroll
        for (int j = 0; j < 4; j++) {
            cP[j][0] *= invA; cP[j][1] *= invA;
            cP[j][2] *= invB; cP[j][3] *= invB;
        }

        // O -> regs, outproj accumulate
        uint32_t OAh[2][4], OAl[2][4];
#pragma unroll
        for (int j = 0; j < 4; j++) {
            int kc = j >> 1, e = j & 1;
            split_pk(cP[j][0], cP[j][1], OAh[kc][2 * e],     OAl[kc][2 * e]);
            split_pk(cP[j][2], cP[j][3], OAh[kc][2 * e + 1], OAl[kc][2 * e + 1]);
        }
#pragma unroll
        for (int kk = 0; kk < 2; kk++) {
#pragma unroll
            for (int j = 0; j < 8; j++) {
                uint32_t bh2[2], bl2[2];
                ldB4(WOb, 5120u, 20, j * 8 * 20 + kk * 8, lane, bh2, bl2);
                mma3(oacc[j], OAh[kk], OAl[kk], bh2, bl2);
            }
        }
    }

    // Deposit into out (zero-initialized by memset). rows = f, cols = d
#pragma unroll
    for (int j = 0; j < 8; j++) {
        int d0 = j * 8 + 2 * t;
        float bo0 = bo_g[d0], bo1 = bo_g[d0 + 1];
        size_t base0 = ((size_t)(b * TT + tt) * FF + rrA) * DD;
        size_t base1 = ((size_t)(b * TT + tt) * FF + rrB) * DD;
        atomicAdd(out + base0 + d0,     oacc[j][0] + bo0);
        atomicAdd(out + base0 + d0 + 1, oacc[j][1] + bo1);
        atomicAdd(out + base1 + d0,     oacc[j][2] + bo0);
        atomicAdd(out + base1 + d0 + 1, oacc[j][3] + bo1);
    }
}

// ---------------------------------------------------------------------------
// Temporal body: id -> (b, f-pair). 2 sub-blocks x 64 rows (T). atomicAdd out.
// K/V visibility barrier is sub-local (named barrier), halving coupling.
// ---------------------------------------------------------------------------
__device__ __forceinline__ void temporal_body(
    uint32_t* smw, int id,
    const float* __restrict__ x,
    const uint4* __restrict__ wsrc,
    const float* __restrict__ bq_g, const float* __restrict__ bk_g,
    const float* __restrict__ bv_g, const float* __restrict__ bo_g,
    float* __restrict__ out)
{
    uint32_t* XH  = smw;            // 2 x (64 x 36)
    uint32_t* XL  = smw + 4608;
    uint32_t* KTH = smw + 18688;    // 2 x (64 x 20)
    uint32_t* KTL = smw + 21248;
    uint32_t* VTH = smw + 23808;    // 2 x (32 x 36)
    uint32_t* VTL = smw + 26112;    // -> 28416

    const int tid  = threadIdx.x;
    const int lane = tid & 31;
    const int w    = tid >> 5;
    const int g    = lane >> 2;
    const int t    = lane & 3;
    const int b    = id >> 6;
    const int f0   = (id & 63) * 2;
    const int sub  = w >> 2;
    const int row0 = (w & 3) * 16;
    const int rrA  = row0 + g, rrB = row0 + g + 8;
    const int f    = f0 + sub;

    uint32_t* KTHs = KTH + sub * 1280;
    uint32_t* KTLs = KTL + sub * 1280;
    uint32_t* VTHs = VTH + sub * 1152;
    uint32_t* VTLs = VTL + sub * 1152;

    const uint32_t sb  = (uint32_t)__cvta_generic_to_shared(smw);
    const uint32_t XHb = sb + (uint32_t)(sub * 2304) * 4u;   // XL delta = 18432 B
    const uint32_t WCb = sb + 9216u * 4u;                    // lo delta = 13824 B
    const uint32_t WOb = sb + 16128u * 4u;                   // lo delta = 5120 B
    const uint32_t KTb = sb + (18688u + (uint32_t)(sub * 1280)) * 4u;  // lo delta 10240 B
    const uint32_t VTb = sb + (23808u + (uint32_t)(sub * 1152)) * 4u;  // lo delta 9216 B

    // Stage x slices for both f's
    for (int i = tid; i < 2 * 64 * 32; i += 256) {
        int s = i >> 11, rem = i & 2047, row = rem >> 5, dp = rem & 31;
        const float* xp = x + ((size_t)(b * TT + row) * FF + (f0 + s)) * DD;
        float2 v = *(const float2*)(xp + 2 * dp);
        split_pk(v.x, v.y, XH[s * 2304 + row * 36 + dp], XL[s * 2304 + row * 36 + dp]);
    }

    float oacc[8][4];
#pragma unroll
    for (int j = 0; j < 8; j++)
#pragma unroll
        for (int i = 0; i < 4; i++) oacc[j][i] = 0.f;

    for (int h = 0; h < HH; h++) {
        __syncthreads();
        {
            const uint4* srcv = wsrc + (size_t)h * 2368;
            uint4* dstv = (uint4*)(smw + 9216);
            for (int i = tid; i < 2368; i += 256) dstv[i] = srcv[i];
        }
        __syncthreads();

        // --- GEMM1 ---
        float c12[12][4];
#pragma unroll
        for (int j = 0; j < 12; j++)
#pragma unroll
            for (int i = 0; i < 4; i++) c12[j][i] = 0.f;
        for (int kk = 0; kk < 4; kk++) {
            uint32_t ah[4], al[4];
            ldA4(XHb, 36, row0 * 36 + kk * 8, lane, ah);
            ldA4(XHb + 18432u, 36, row0 * 36 + kk * 8, lane, al);
#pragma unroll
            for (int j = 0; j < 12; j++) {
                uint32_t bh2[2], bl2[2];
                ldB4(WCb, 13824u, 36, j * 8 * 36 + kk * 8, lane, bh2, bl2);
                mma3(c12[j], ah, al, bh2, bl2);
            }
        }
        uint32_t QAh[2][4], QAl[2][4];
#pragma unroll
        for (int j = 0; j < 4; j++) {
            int cc = j * 8 + 2 * t;
            float b0 = bq_g[h * 32 + cc], b1 = bq_g[h * 32 + cc + 1];
            float v0 = (c12[j][0] + b0) * QSCALE, v1 = (c12[j][1] + b1) * QSCALE;
            float v2 = (c12[j][2] + b0) * QSCALE, v3 = (c12[j][3] + b1) * QSCALE;
            int kc = j >> 1, e = j & 1;
            split_pk(v0, v1, QAh[kc][2 * e],     QAl[kc][2 * e]);
            split_pk(v2, v3, QAh[kc][2 * e + 1], QAl[kc][2 * e + 1]);
        }
#pragma unroll
        for (int j = 4; j < 8; j++) {
            int cc = (j - 4) * 8 + 2 * t;
            float b0 = bk_g[h * 32 + cc], b1 = bk_g[h * 32 + cc + 1];
            int kp = cc >> 1;
            split_pk(c12[j][0] + b0, c12[j][1] + b1, KTHs[rrA * 20 + kp], KTLs[rrA * 20 + kp]);
            split_pk(c12[j][2] + b0, c12[j][3] + b1, KTHs[rrB * 20 + kp], KTLs[rrB * 20 + kp]);
        }
        {
            __nv_bfloat16* vh = reinterpret_cast<__nv_bfloat16*>(VTHs);
            __nv_bfloat16* vl = reinterpret_cast<__nv_bfloat16*>(VTLs);
#pragma unroll
            for (int j = 8; j < 12; j++) {
                int vk = (j - 8) * 8 + 2 * t;
                float b0 = bv_g[h * 32 + vk], b1 = bv_g[h * 32 + vk + 1];
                float vv[4] = {c12[j][0] + b0, c12[j][1] + b1, c12[j][2] + b0, c12[j][3] + b1};
                int   cl[4] = {vk, vk + 1, vk, vk + 1};
                int   rw[4] = {rrA, rrA, rrB, rrB};
#pragma unroll
                for (int q2 = 0; q2 < 4; q2++) {
                    __nv_bfloat16 hb = __float2bfloat16(vv[q2]);
                    float lf = vv[q2] - __bfloat162float(hb);
                    vh[cl[q2] * 72 + rw[q2]] = hb;
                    vl[cl[q2] * 72 + rw[q2]] = __float2bfloat16(lf);
                }
            }
        }
        // K/V of this sub written/read only by this sub's 4 warps: sub-local barrier
        asm volatile("bar.sync %0, %1;" :: "r"(1 + sub), "r"(128) : "memory");

        // --- S = Q K^T over 64 cols, full-row softmax ---
        float cS[8][4];
#pragma unroll
        for (int j = 0; j < 8; j++)
#pragma unroll
            for (int i = 0; i < 4; i++) cS[j][i] = 0.f;
#pragma unroll
        for (int kk = 0; kk < 2; kk++) {
#pragma unroll
            for (int j = 0; j < 8; j++) {
                uint32_t bh2[2], bl2[2];
                ldB4(KTb, 10240u, 20, j * 8 * 20 + kk * 8, lane, bh2, bl2);
                mma3(cS[j], QAh[kk], QAl[kk], bh2, bl2);
            }
        }
        float mA = cS[0][0], mB = cS[0][2];
#pragma unroll
        for (int j = 0; j < 8; j++) {
            mA = fmaxf(mA, fmaxf(cS[j][0], cS[j][1]));
            mB = fmaxf(mB, fmaxf(cS[j][2], cS[j][3]));
        }
        mA = fmaxf(mA, __shfl_xor_sync(0xffffffff, mA, 1));
        mA = fmaxf(mA, __shfl_xor_sync(0xffffffff, mA, 2));
        mB = fmaxf(mB, __shfl_xor_sync(0xffffffff, mB, 1));
        mB = fmaxf(mB, __shfl_xor_sync(0xffffffff, mB, 2));
        float sA = 0.f, sB = 0.f;
#pragma unroll
        for (int j = 0; j < 8; j++) {
            cS[j][0] = ex2f(cS[j][0] - mA); sA += cS[j][0];
            cS[j][1] = ex2f(cS[j][1] - mA); sA += cS[j][1];
            cS[j][2] = ex2f(cS[j][2] - mB); sB += cS[j][2];
            cS[j][3] = ex2f(cS[j][3] - mB); sB += cS[j][3];
        }
        sA += __shfl_xor_sync(0xffffffff, sA, 1);
        sA += __shfl_xor_sync(0xffffffff, sA, 2);
        sB += __shfl_xor_sync(0xffffffff, sB, 1);
        sB += __shfl_xor_sync(0xffffffff, sB, 2);
        float invA = __fdividef(1.f, sA), invB = __fdividef(1.f, sB);

        // P -> regs (A-frags for PV)
        uint32_t PAh[4][4], PAl[4][4];
#pragma unroll
        for (int kc = 0; kc < 4; kc++) {
            int j0 = 2 * kc;
            split_pk(cS[j0][0] * invA,     cS[j0][1] * invA,     PAh[kc][0], PAl[kc][0]);
            split_pk(cS[j0][2] * invB,     cS[j0][3] * invB,     PAh[kc][1], PAl[kc][1]);
            split_pk(cS[j0 + 1][0] * invA, cS[j0 + 1][1] * invA, PAh[kc][2], PAl[kc][2]);
            split_pk(cS[j0 + 1][2] * invB, cS[j0 + 1][3] * invB, PAh[kc][3], PAl[kc][3]);
        }

        // --- PV ---
        float cP[4][4];
#pragma unroll
        for (int j = 0; j < 4; j++)
#pragma unroll
            for (int i = 0; i < 4; i++) cP[j][i] = 0.f;
#pragma unroll
        for (int kk = 0; kk < 4; kk++) {
#pragma unroll
            for (int j = 0; j < 4; j++) {
                uint32_t bh2[2], bl2[2];
                ldB4(VTb, 9216u, 36, j * 8 * 36 + kk * 8, lane, bh2, bl2);
                mma3(cP[j], PAh[kk], PAl[kk], bh2, bl2);
            }
        }

        // O -> regs, outproj accumulate
        uint32_t OAh[2][4], OAl[2][4];
#pragma unroll
        for (int j = 0; j < 4; j++) {
            int kc = j >> 1, e = j & 1;
            split_pk(cP[j][0], cP[j][1], OAh[kc][2 * e],     OAl[kc][2 * e]);
            split_pk(cP[j][2], cP[j][3], OAh[kc][2 * e + 1], OAl[kc][2 * e + 1]);
        }
#pragma unroll
        for (int kk = 0; kk < 2; kk++) {
#pragma unroll
            for (int j = 0; j < 8; j++) {
                uint32_t bh2[2], bl2[2];
                ldB4(WOb, 5120u, 20, j * 8 * 20 + kk * 8, lane, bh2, bl2);
                mma3(oacc[j], OAh[kk], OAl[kk], bh2, bl2);
            }
        }
    }

    // Deposit into out (zero-initialized by memset). rows = t, cols = d
#pragma unroll
    for (int j = 0; j < 8; j++) {
        int d0 = j * 8 + 2 * t;
        float bo0 = bo_g[d0], bo1 = bo_g[d0 + 1];
        size_t base0 = ((size_t)(b * TT + rrA) * FF + f) * DD;
        size_t base1 = ((size_t)(b * TT + rrB) * FF + f) * DD;
        atomicAdd(out + base0 + d0,     oacc[j][0] + bo0);
        atomicAdd(out + base0 + d0 + 1, oacc[j][1] + bo1);
        atomicAdd(out + base1 + d0,     oacc[j][2] + bo0);
        atomicAdd(out + base1 + d0 + 1, oacc[j][3] + bo1);
    }
}

// ---------------------------------------------------------------------------
// Fused kernel: even blocks -> temporal, odd blocks -> feature (interleaved).
// ---------------------------------------------------------------------------
__global__ __launch_bounds__(256, 2) void fused_kernel(
    const float* __restrict__ x,
    const float* __restrict__ tqb, const float* __restrict__ tkb,
    const float* __restrict__ tvb, const float* __restrict__ tob,
    const float* __restrict__ fqb, const float* __restrict__ fkb,
    const float* __restrict__ fvb, const float* __restrict__ fob,
    float* __restrict__ out)
{
    extern __shared__ uint32_t smw[];
    int id = blockIdx.x >> 1;
    if ((blockIdx.x & 1) == 0) {
        temporal_body(smw, id, x, &g_w[0][0][0], tqb, tkb, tvb, tob, out);
    } else {
        feature_body(smw, id, x, &g_w[1][0][0], fqb, fkb, fvb, fob, out);
    }
}

extern "C" void kernel_launch(void* const* d_in, const int* in_sizes, int n_in,
                              void* d_out, int out_size)
{
    const float* x = (const float*)d_in[0];
    const float *tqw, *tqb, *tkw, *tkb, *tvw, *tvb, *tow, *tob;
    const float *fqw, *fqb, *fkw, *fkb, *fvw, *fvb, *fow, *fob;

    if (in_sizes[8] == 64) {  // reference-signature order
        tqw = (const float*)d_in[1];  tqb = (const float*)d_in[2];
        tkw = (const float*)d_in[3];  tkb = (const float*)d_in[4];
        tvw = (const float*)d_in[5];  tvb = (const float*)d_in[6];
        tow = (const float*)d_in[7];  tob = (const float*)d_in[8];
        fqw = (const float*)d_in[9];  fqb = (const float*)d_in[10];
        fkw = (const float*)d_in[11]; fkb = (const float*)d_in[12];
        fvw = (const float*)d_in[13]; fvb = (const float*)d_in[14];
        fow = (const float*)d_in[15]; fob = (const float*)d_in[16];
    } else {                  // setup_inputs dict order
        tqw = (const float*)d_in[1];  tqb = (const float*)d_in[2];
        tkw = (const float*)d_in[3];  tkb = (const float*)d_in[4];
        tvw = (const float*)d_in[5];  tvb = (const float*)d_in[6];
        fqw = (const float*)d_in[7];  fqb = (const float*)d_in[8];
        fkw = (const float*)d_in[9];  fkb = (const float*)d_in[10];
        fvw = (const float*)d_in[11]; fvb = (const float*)d_in[12];
        tow = (const float*)d_in[13]; tob = (const float*)d_in[14];
        fow = (const float*)d_in[15]; fob = (const float*)d_in[16];
    }

    const int SMEM = 28416 * 4;     // 113664 B -> 2 CTA/SM
    cudaFuncSetAttribute(fused_kernel,
                         cudaFuncAttributeMaxDynamicSharedMemorySize, SMEM);

    cudaMemsetAsync(d_out, 0, (size_t)out_size * sizeof(float), 0);
    prep_kernel<<<8, 256>>>(tqw, tkw, tvw, tow, fqw, fkw, fvw, fow);
    fused_kernel<<<4096, 256, SMEM>>>(
        x, tqb, tkb, tvb, tob, fqb, fkb, fvb, fob, (float*)d_out);
}